// round 1
// baseline (speedup 1.0000x reference)
#include <cuda_runtime.h>
#include <math.h>

// Problem constants
#define T_DIM 2048
#define B_DIM 2
#define E_DIM 1024
#define H_DIM 16
#define DH    64
#define MROWS (T_DIM * B_DIM)   // 4096

// Scratch (device globals — no allocation allowed)
__device__ float g_q[MROWS * E_DIM];
__device__ float g_k[MROWS * E_DIM];
__device__ float g_v[MROWS * E_DIM];
__device__ float g_attn[MROWS * E_DIM];

// ---------------------------------------------------------------------------
// GEMM: C = (A @ W^T + bias) * alpha
// A: [M, K] row-major, W: [N, K] row-major (nn.Linear weight), C: [M, N]
// M = 4096, N = K = 1024 (all multiples of tile sizes; no bounds checks)
// ---------------------------------------------------------------------------
#define BM 128
#define BN 128
#define BK 16
#define TM 8
#define TN 8
// 256 threads = 16x16, each computes an 8x8 register tile

__device__ __forceinline__ void gemm_nt_body(const float* __restrict__ A,
                                             const float* __restrict__ W,
                                             const float* __restrict__ bias,
                                             float* __restrict__ C,
                                             float alpha)
{
    const int K = E_DIM;
    const int N = E_DIM;
    __shared__ float As[BK][BM + 4];
    __shared__ float Bs[BK][BN + 4];

    const int tid = threadIdx.x;
    const int tx  = tid & 15;
    const int ty  = tid >> 4;
    const int row0 = blockIdx.y * BM;
    const int col0 = blockIdx.x * BN;

    // global->shared load mapping: 128 rows x 16 k, float4 per thread, 2 iters
    const int lr = tid >> 2;            // 0..63
    const int lc = (tid & 3) << 2;      // 0,4,8,12

    float acc[TM][TN];
#pragma unroll
    for (int i = 0; i < TM; i++)
#pragma unroll
        for (int j = 0; j < TN; j++) acc[i][j] = 0.f;

    for (int k0 = 0; k0 < K; k0 += BK) {
#pragma unroll
        for (int it = 0; it < 2; it++) {
            int r = lr + it * 64;
            float4 va = *(const float4*)(A + (size_t)(row0 + r) * K + k0 + lc);
            As[lc + 0][r] = va.x; As[lc + 1][r] = va.y;
            As[lc + 2][r] = va.z; As[lc + 3][r] = va.w;
            float4 vb = *(const float4*)(W + (size_t)(col0 + r) * K + k0 + lc);
            Bs[lc + 0][r] = vb.x; Bs[lc + 1][r] = vb.y;
            Bs[lc + 2][r] = vb.z; Bs[lc + 3][r] = vb.w;
        }
        __syncthreads();

#pragma unroll
        for (int k = 0; k < BK; k++) {
            float4 a0 = *(const float4*)&As[k][ty * TM];
            float4 a1 = *(const float4*)&As[k][ty * TM + 4];
            float4 b0 = *(const float4*)&Bs[k][tx * TN];
            float4 b1 = *(const float4*)&Bs[k][tx * TN + 4];
            float ra[8] = {a0.x, a0.y, a0.z, a0.w, a1.x, a1.y, a1.z, a1.w};
            float rb[8] = {b0.x, b0.y, b0.z, b0.w, b1.x, b1.y, b1.z, b1.w};
#pragma unroll
            for (int i = 0; i < TM; i++)
#pragma unroll
                for (int j = 0; j < TN; j++)
                    acc[i][j] = fmaf(ra[i], rb[j], acc[i][j]);
        }
        __syncthreads();
    }

#pragma unroll
    for (int i = 0; i < TM; i++) {
        int row = row0 + ty * TM + i;
#pragma unroll
        for (int j = 0; j < TN; j += 4) {
            int col = col0 + tx * TN + j;
            float4 o;
            o.x = (acc[i][j + 0] + bias[col + 0]) * alpha;
            o.y = (acc[i][j + 1] + bias[col + 1]) * alpha;
            o.z = (acc[i][j + 2] + bias[col + 2]) * alpha;
            o.w = (acc[i][j + 3] + bias[col + 3]) * alpha;
            *(float4*)(C + (size_t)row * N + col) = o;
        }
    }
}

__global__ void __launch_bounds__(256)
qkv_kernel(const float* __restrict__ X,
           const float* __restrict__ Wq, const float* __restrict__ bq,
           const float* __restrict__ Wk, const float* __restrict__ bk,
           const float* __restrict__ Wv, const float* __restrict__ bv)
{
    if (blockIdx.z == 0)      gemm_nt_body(X, Wq, bq, g_q, 0.125f);  // scale = Dh^-0.5
    else if (blockIdx.z == 1) gemm_nt_body(X, Wk, bk, g_k, 1.0f);
    else                      gemm_nt_body(X, Wv, bv, g_v, 1.0f);
}

__global__ void __launch_bounds__(256)
oproj_kernel(const float* __restrict__ Wo, const float* __restrict__ bo,
             float* __restrict__ out)
{
    gemm_nt_body(g_attn, Wo, bo, out, 1.0f);
}

// ---------------------------------------------------------------------------
// Flash attention (fp32, causal). One block per (q-tile, head).
// Br = Bc = 64, Dh = 64. 256 threads = 16x16; thread owns 4x4 of S and 4x4 of O.
// q already scaled by Dh^-0.5 in projection.
// Layout: head = b*H + h; row (t) lives at g_q[((t)*B + b)*E + h*Dh + d].
// Output written directly into [T, B, E] layout (g_attn).
// ---------------------------------------------------------------------------
#define BR 64
#define BC 64
#define SPITCH 68   // row pitch in floats (pad 4: keeps float4 alignment)

__global__ void __launch_bounds__(256)
flash_kernel()
{
    extern __shared__ float sm[];
    float* Qs = sm;                       // [64][68]
    float* Ks = Qs + 64 * SPITCH;         // [64][68]
    float* Vs = Ks + 64 * SPITCH;         // [64][68]
    float* Ps = Vs + 64 * SPITCH;         // [64][68]

    const int tid = threadIdx.x;
    const int tx  = tid & 15;
    const int ty  = tid >> 4;
    const int qt   = blockIdx.x;          // q tile 0..31
    const int head = blockIdx.y;          // 0..31 = b*H + h
    const int b = head / H_DIM;
    const int h = head % H_DIM;
    const int i0 = qt * BR;
    const int ri = ty * 4;                // this thread's S/O row base (local)
    const int cj = tx * 4;                // this thread's S col base / O col base
    const size_t colbase = (size_t)h * DH;

    // Load Q tile once
    for (int idx = tid; idx < 64 * 16; idx += 256) {
        int r  = idx >> 4;
        int c4 = (idx & 15) << 2;
        float4 v = *(const float4*)(g_q + ((size_t)(i0 + r) * B_DIM + b) * E_DIM + colbase + c4);
        *(float4*)&Qs[r * SPITCH + c4] = v;
    }

    float m_i[4], l_i[4], o[4][4];
#pragma unroll
    for (int i = 0; i < 4; i++) {
        m_i[i] = -1e30f; l_i[i] = 0.f;
#pragma unroll
        for (int j = 0; j < 4; j++) o[i][j] = 0.f;
    }

    for (int kt = 0; kt <= qt; kt++) {
        __syncthreads();  // previous iter's Ks/Vs/Ps fully consumed (also covers Qs on kt=0)
        const int t0 = kt * BC;
        for (int idx = tid; idx < 64 * 16; idx += 256) {
            int r  = idx >> 4;
            int c4 = (idx & 15) << 2;
            size_t goff = ((size_t)(t0 + r) * B_DIM + b) * E_DIM + colbase + c4;
            *(float4*)&Ks[r * SPITCH + c4] = *(const float4*)(g_k + goff);
            *(float4*)&Vs[r * SPITCH + c4] = *(const float4*)(g_v + goff);
        }
        __syncthreads();

        // S = Q @ K^T for this thread's 4x4 tile
        float s[4][4];
#pragma unroll
        for (int i = 0; i < 4; i++)
#pragma unroll
            for (int j = 0; j < 4; j++) s[i][j] = 0.f;

#pragma unroll 4
        for (int d = 0; d < DH; d += 4) {
            float4 qv[4], kv[4];
#pragma unroll
            for (int i = 0; i < 4; i++) qv[i] = *(const float4*)&Qs[(ri + i) * SPITCH + d];
#pragma unroll
            for (int j = 0; j < 4; j++) kv[j] = *(const float4*)&Ks[(cj + j) * SPITCH + d];
#pragma unroll
            for (int i = 0; i < 4; i++)
#pragma unroll
                for (int j = 0; j < 4; j++) {
                    s[i][j] = fmaf(qv[i].x, kv[j].x, s[i][j]);
                    s[i][j] = fmaf(qv[i].y, kv[j].y, s[i][j]);
                    s[i][j] = fmaf(qv[i].z, kv[j].z, s[i][j]);
                    s[i][j] = fmaf(qv[i].w, kv[j].w, s[i][j]);
                }
        }

        // causal mask on the diagonal tile (local coords: col > row masked)
        if (kt == qt) {
#pragma unroll
            for (int i = 0; i < 4; i++)
#pragma unroll
                for (int j = 0; j < 4; j++)
                    if (cj + j > ri + i) s[i][j] = -1e30f;
        }

        // online softmax update (row stats reduced across the 16-lane tx group)
#pragma unroll
        for (int i = 0; i < 4; i++) {
            float rm = fmaxf(fmaxf(s[i][0], s[i][1]), fmaxf(s[i][2], s[i][3]));
#pragma unroll
            for (int off = 1; off < 16; off <<= 1)
                rm = fmaxf(rm, __shfl_xor_sync(0xffffffffu, rm, off));
            float mnew = fmaxf(m_i[i], rm);
            float corr = __expf(m_i[i] - mnew);
            float rs = 0.f;
#pragma unroll
            for (int j = 0; j < 4; j++) {
                s[i][j] = __expf(s[i][j] - mnew);
                rs += s[i][j];
            }
#pragma unroll
            for (int off = 1; off < 16; off <<= 1)
                rs += __shfl_xor_sync(0xffffffffu, rs, off);
            l_i[i] = l_i[i] * corr + rs;
            m_i[i] = mnew;
#pragma unroll
            for (int j = 0; j < 4; j++) o[i][j] *= corr;
        }

        // stage P to shared for the PV product
#pragma unroll
        for (int i = 0; i < 4; i++)
            *(float4*)&Ps[(ri + i) * SPITCH + cj] = make_float4(s[i][0], s[i][1], s[i][2], s[i][3]);
        __syncthreads();

        // O += P @ V  (contract over the 64 local kv rows)
#pragma unroll 8
        for (int jj = 0; jj < BC; jj++) {
            float4 vv = *(const float4*)&Vs[jj * SPITCH + cj];
            float p0 = Ps[(ri + 0) * SPITCH + jj];
            float p1 = Ps[(ri + 1) * SPITCH + jj];
            float p2 = Ps[(ri + 2) * SPITCH + jj];
            float p3 = Ps[(ri + 3) * SPITCH + jj];
            o[0][0] = fmaf(p0, vv.x, o[0][0]); o[0][1] = fmaf(p0, vv.y, o[0][1]);
            o[0][2] = fmaf(p0, vv.z, o[0][2]); o[0][3] = fmaf(p0, vv.w, o[0][3]);
            o[1][0] = fmaf(p1, vv.x, o[1][0]); o[1][1] = fmaf(p1, vv.y, o[1][1]);
            o[1][2] = fmaf(p1, vv.z, o[1][2]); o[1][3] = fmaf(p1, vv.w, o[1][3]);
            o[2][0] = fmaf(p2, vv.x, o[2][0]); o[2][1] = fmaf(p2, vv.y, o[2][1]);
            o[2][2] = fmaf(p2, vv.z, o[2][2]); o[2][3] = fmaf(p2, vv.w, o[2][3]);
            o[3][0] = fmaf(p3, vv.x, o[3][0]); o[3][1] = fmaf(p3, vv.y, o[3][1]);
            o[3][2] = fmaf(p3, vv.z, o[3][2]); o[3][3] = fmaf(p3, vv.w, o[3][3]);
        }
    }

    // finalize: normalize and write to [T, B, E] layout
#pragma unroll
    for (int i = 0; i < 4; i++) {
        float inv = 1.f / l_i[i];
        float4 ov = make_float4(o[i][0] * inv, o[i][1] * inv, o[i][2] * inv, o[i][3] * inv);
        *(float4*)(g_attn + ((size_t)(i0 + ri + i) * B_DIM + b) * E_DIM + colbase + cj) = ov;
    }
}

// ---------------------------------------------------------------------------
// kernel_launch
// Inputs (metadata order): query, Wq, bq, Wk, bk, Wv, bv, Wo, bo, attn_mask
// attn_mask is ignored (known causal structure).
// ---------------------------------------------------------------------------
extern "C" void kernel_launch(void* const* d_in, const int* in_sizes, int n_in,
                              void* d_out, int out_size)
{
    const float* query = (const float*)d_in[0];
    const float* Wq    = (const float*)d_in[1];
    const float* bq    = (const float*)d_in[2];
    const float* Wk    = (const float*)d_in[3];
    const float* bk    = (const float*)d_in[4];
    const float* Wv    = (const float*)d_in[5];
    const float* bv    = (const float*)d_in[6];
    const float* Wo    = (const float*)d_in[7];
    const float* bo    = (const float*)d_in[8];
    float* out = (float*)d_out;

    const int flash_smem = 4 * 64 * SPITCH * sizeof(float);  // 69632 bytes
    cudaFuncSetAttribute(flash_kernel, cudaFuncAttributeMaxDynamicSharedMemorySize, flash_smem);

    // QKV projections (z selects Q/K/V)
    qkv_kernel<<<dim3(E_DIM / BN, MROWS / BM, 3), 256>>>(query, Wq, bq, Wk, bk, Wv, bv);

    // causal flash attention: 32 q-tiles x 32 heads
    flash_kernel<<<dim3(T_DIM / BR, B_DIM * H_DIM), 256, flash_smem>>>();

    // output projection
    oproj_kernel<<<dim3(E_DIM / BN, MROWS / BM), 256>>>(Wo, bo, out);
}

// round 3
// speedup vs baseline: 2.4298x; 2.4298x over previous
#include <cuda_runtime.h>
#include <cuda_bf16.h>
#include <math.h>
#include <stdint.h>

// Problem constants
#define T_DIM 2048
#define B_DIM 2
#define E_DIM 1024
#define H_DIM 16
#define DH    64
#define MROWS (T_DIM * B_DIM)   // 4096

// Scratch (device globals — no allocation allowed)
__device__ float g_q[MROWS * E_DIM];
__device__ float g_k[MROWS * E_DIM];
__device__ float g_v[MROWS * E_DIM];
__device__ float g_attn[MROWS * E_DIM];

// ===========================================================================
// Helpers
// ===========================================================================
__device__ __forceinline__ uint32_t smem_u32(const void* p) {
    uint32_t a;
    asm("{ .reg .u64 t; cvta.to.shared.u64 t, %1; cvt.u32.u64 %0, t; }" : "=r"(a) : "l"(p));
    return a;
}

#define LDSM4(R0, R1, R2, R3, ADDR) \
    asm volatile("ldmatrix.sync.aligned.m8n8.x4.shared.b16 {%0,%1,%2,%3}, [%4];" \
                 : "=r"(R0), "=r"(R1), "=r"(R2), "=r"(R3) : "r"(ADDR))

#define LDSM4T(R0, R1, R2, R3, ADDR) \
    asm volatile("ldmatrix.sync.aligned.m8n8.x4.trans.shared.b16 {%0,%1,%2,%3}, [%4];" \
                 : "=r"(R0), "=r"(R1), "=r"(R2), "=r"(R3) : "r"(ADDR))

// D (f32x4) += A (bf16 m16k16, 4 regs) * B (bf16 k16n8, 2 regs)
#define MMA_BF16(D, A, B0, B1) \
    asm volatile("mma.sync.aligned.m16n8k16.row.col.f32.bf16.bf16.f32 " \
                 "{%0,%1,%2,%3}, {%4,%5,%6,%7}, {%8,%9}, {%0,%1,%2,%3};" \
                 : "+f"((D)[0]), "+f"((D)[1]), "+f"((D)[2]), "+f"((D)[3]) \
                 : "r"((A)[0]), "r"((A)[1]), "r"((A)[2]), "r"((A)[3]), "r"(B0), "r"(B1))

// split one float4 into hi/lo bf16 quads and store 8B each at element offset
__device__ __forceinline__ void split_store(uint16_t* hiA, uint16_t* loA, int off, float4 v) {
    __nv_bfloat162 h01, h23, l01, l23;
    h01.x = __float2bfloat16(v.x); h01.y = __float2bfloat16(v.y);
    h23.x = __float2bfloat16(v.z); h23.y = __float2bfloat16(v.w);
    l01.x = __float2bfloat16(v.x - __bfloat162float(h01.x));
    l01.y = __float2bfloat16(v.y - __bfloat162float(h01.y));
    l23.x = __float2bfloat16(v.z - __bfloat162float(h23.x));
    l23.y = __float2bfloat16(v.w - __bfloat162float(h23.y));
    uint2 hw, lw;
    hw.x = *(uint32_t*)&h01; hw.y = *(uint32_t*)&h23;
    lw.x = *(uint32_t*)&l01; lw.y = *(uint32_t*)&l23;
    *(uint2*)(hiA + off) = hw;
    *(uint2*)(loA + off) = lw;
}

// pack two f32 into bf16x2 hi and residual lo
__device__ __forceinline__ void split_pack(float a, float b, uint32_t& hi, uint32_t& lo) {
    __nv_bfloat162 H, L;
    H.x = __float2bfloat16(a); H.y = __float2bfloat16(b);
    L.x = __float2bfloat16(a - __bfloat162float(H.x));
    L.y = __float2bfloat16(b - __bfloat162float(H.y));
    hi = *(uint32_t*)&H; lo = *(uint32_t*)&L;
}

// fast exp on FMA pipe (no MUFU): deg-5 Taylor of 2^f on [-0.5, 0.5], ~2.4e-6 rel
__device__ __forceinline__ float fast_exp(float x) {
    float y = fmaxf(x * 1.44269504f, -126.0f);
    int   e = __float2int_rn(y);
    float f = y - (float)e;
    float p = 1.33336e-3f;
    p = fmaf(p, f, 9.61812e-3f);
    p = fmaf(p, f, 5.55041e-2f);
    p = fmaf(p, f, 2.402265e-1f);
    p = fmaf(p, f, 6.931472e-1f);
    p = fmaf(p, f, 1.0f);
    return __int_as_float((e + 127) << 23) * p;
}

// ===========================================================================
// Projection GEMM on tensor cores: C = (A @ W^T + bias) * alpha
// A:[4096,1024] f32, W:[1024,1024] f32. CTA 128x128, 8 warps (2x4), BK=32.
// 3-term bf16 split. Smem pitch 40 bf16 (80B) -> conflict-free ldmatrix.
// ===========================================================================
#define PPITCH 40

__device__ __forceinline__ void gemm_mma(const float* __restrict__ A,
                                         const float* __restrict__ W,
                                         const float* __restrict__ bias,
                                         float* __restrict__ C,
                                         float alpha)
{
    __shared__ uint16_t sAh[128 * PPITCH], sAl[128 * PPITCH];
    __shared__ uint16_t sBh[128 * PPITCH], sBl[128 * PPITCH];

    const int tid  = threadIdx.x;
    const int lane = tid & 31;
    const int wid  = tid >> 5;
    const int wy   = wid >> 2;     // 0..1
    const int wx   = wid & 3;      // 0..3
    const int row0 = blockIdx.y * 128;
    const int col0 = blockIdx.x * 128;

    const uint32_t aHb = smem_u32(sAh), aLb = smem_u32(sAl);
    const uint32_t bHb = smem_u32(sBh), bLb = smem_u32(sBl);

    // ldmatrix per-thread element offsets
    const int aOff = (wy * 64 + (lane & 15)) * PPITCH + ((lane >> 4) & 1) * 8;
    const int bOff = (wx * 32 + (lane & 7) + ((lane >> 4) & 1) * 8) * PPITCH + ((lane >> 3) & 1) * 8;

    float acc[4][4][4];
#pragma unroll
    for (int i = 0; i < 4; i++)
#pragma unroll
        for (int j = 0; j < 4; j++)
#pragma unroll
            for (int k = 0; k < 4; k++) acc[i][j][k] = 0.f;

    for (int k0 = 0; k0 < E_DIM; k0 += 32) {
        __syncthreads();
#pragma unroll
        for (int i = 0; i < 4; ++i) {
            int g = tid + i * 256;            // 0..1023
            int r = g >> 3, c4 = (g & 7) << 2;
            float4 va = *(const float4*)(A + (size_t)(row0 + r) * E_DIM + k0 + c4);
            split_store(sAh, sAl, r * PPITCH + c4, va);
            float4 vb = *(const float4*)(W + (size_t)(col0 + r) * E_DIM + k0 + c4);
            split_store(sBh, sBl, r * PPITCH + c4, vb);
        }
        __syncthreads();

#pragma unroll
        for (int kb = 0; kb < 2; ++kb) {
            uint32_t bh[4][2], bl[4][2];
#pragma unroll
            for (int np = 0; np < 2; ++np) {
                int boe = bOff + np * 16 * PPITCH + kb * 16;
                LDSM4(bh[2 * np][0], bh[2 * np][1], bh[2 * np + 1][0], bh[2 * np + 1][1],
                      bHb + boe * 2);
                LDSM4(bl[2 * np][0], bl[2 * np][1], bl[2 * np + 1][0], bl[2 * np + 1][1],
                      bLb + boe * 2);
            }
#pragma unroll
            for (int mf = 0; mf < 4; ++mf) {
                uint32_t ah[4], al[4];
                int aoe = aOff + mf * 16 * PPITCH + kb * 16;
                LDSM4(ah[0], ah[1], ah[2], ah[3], aHb + aoe * 2);
                LDSM4(al[0], al[1], al[2], al[3], aLb + aoe * 2);
#pragma unroll
                for (int nf = 0; nf < 4; ++nf) {
                    MMA_BF16(acc[mf][nf], ah, bh[nf][0], bh[nf][1]);
                    MMA_BF16(acc[mf][nf], ah, bl[nf][0], bl[nf][1]);
                    MMA_BF16(acc[mf][nf], al, bh[nf][0], bh[nf][1]);
                }
            }
        }
    }

    // epilogue
#pragma unroll
    for (int mf = 0; mf < 4; ++mf) {
        int r = row0 + wy * 64 + mf * 16 + (lane >> 2);
#pragma unroll
        for (int nf = 0; nf < 4; ++nf) {
            int col = col0 + wx * 32 + nf * 8 + ((lane & 3) << 1);
            float b0 = bias[col], b1 = bias[col + 1];
            float2 v0 = make_float2((acc[mf][nf][0] + b0) * alpha, (acc[mf][nf][1] + b1) * alpha);
            float2 v1 = make_float2((acc[mf][nf][2] + b0) * alpha, (acc[mf][nf][3] + b1) * alpha);
            *(float2*)(C + (size_t)r * E_DIM + col)       = v0;
            *(float2*)(C + (size_t)(r + 8) * E_DIM + col) = v1;
        }
    }
}

__global__ void __launch_bounds__(256)
qkv_kernel(const float* __restrict__ X,
           const float* __restrict__ Wq, const float* __restrict__ bq,
           const float* __restrict__ Wk, const float* __restrict__ bk,
           const float* __restrict__ Wv, const float* __restrict__ bv)
{
    if (blockIdx.z == 0)      gemm_mma(X, Wq, bq, g_q, 0.125f);  // Dh^-0.5
    else if (blockIdx.z == 1) gemm_mma(X, Wk, bk, g_k, 1.0f);
    else                      gemm_mma(X, Wv, bv, g_v, 1.0f);
}

__global__ void __launch_bounds__(256)
oproj_kernel(const float* __restrict__ Wo, const float* __restrict__ bo,
             float* __restrict__ out)
{
    gemm_mma(g_attn, Wo, bo, out, 1.0f);
}

// ===========================================================================
// Flash attention on tensor cores (causal).
// BR=128 (8 warps x m16), BC=64, Dh=64. 3-term bf16 split for S and PV.
// Smem (bf16, pitch 72): Qh/Ql [128x64], Kh/Kl [64x64], Vh/Vl [64x64] = 72KB.
// ===========================================================================
#define FPITCH 72
#define SQH 0
#define SQL (128 * FPITCH)            // 9216
#define SKH (2 * 128 * FPITCH)        // 18432
#define SKL (SKH + 64 * FPITCH)       // 23040
#define SVH (SKL + 64 * FPITCH)       // 27648
#define SVL (SVH + 64 * FPITCH)       // 32256
#define FSM_ELEMS (SVL + 64 * FPITCH) // 36864 elems = 73728 B

__global__ void __launch_bounds__(256)
flash_mma_kernel()
{
    extern __shared__ uint16_t sm[];
    uint16_t* qh = sm + SQH; uint16_t* ql = sm + SQL;
    uint16_t* kh = sm + SKH; uint16_t* kl = sm + SKL;
    uint16_t* vh = sm + SVH; uint16_t* vl = sm + SVL;

    const int tid  = threadIdx.x;
    const int lane = tid & 31;
    const int w    = tid >> 5;            // warp 0..7 -> rows w*16..
    const int qt   = blockIdx.x;          // 0..15
    const int head = blockIdx.y;          // 0..31
    const int b    = head >> 4;
    const int h    = head & 15;
    const int i0   = qt * 128;
    const size_t colbase = (size_t)h * DH;

    const uint32_t qhB = smem_u32(qh), qlB = smem_u32(ql);
    const uint32_t khB = smem_u32(kh), klB = smem_u32(kl);
    const uint32_t vhB = smem_u32(vh), vlB = smem_u32(vl);

    // ldmatrix per-thread element offsets
    const int qOff = (w * 16 + (lane & 15)) * FPITCH + ((lane >> 4) & 1) * 8;
    const int kOff = ((lane & 7) + ((lane >> 4) & 1) * 8) * FPITCH + ((lane >> 3) & 1) * 8;
    const int vOff = ((lane & 7) + ((lane >> 3) & 1) * 8) * FPITCH + ((lane >> 4) & 1) * 8;

    // load Q tile (scaled q already)
#pragma unroll
    for (int i = 0; i < 8; ++i) {
        int g = tid + i * 256;            // 0..2047
        int r = g >> 4, c4 = (g & 15) << 2;
        float4 v = *(const float4*)(g_q + ((size_t)(i0 + r) * B_DIM + b) * E_DIM + colbase + c4);
        split_store(qh, ql, r * FPITCH + c4, v);
    }

    float s_m[2] = {-1e9f, -1e9f};
    float s_l[2] = {0.f, 0.f};
    float o[8][4];
#pragma unroll
    for (int i = 0; i < 8; i++)
#pragma unroll
        for (int j = 0; j < 4; j++) o[i][j] = 0.f;

    const int rg0 = i0 + w * 16 + (lane >> 2);   // global row (half 0); half1 = +8
    const int ktmax = 2 * qt + 1;

    for (int kt = 0; kt <= ktmax; ++kt) {
        __syncthreads();
        const int j0 = kt * 64;
#pragma unroll
        for (int i = 0; i < 4; ++i) {
            int g = tid + i * 256;        // 0..1023
            int r = g >> 4, c4 = (g & 15) << 2;
            size_t off = ((size_t)(j0 + r) * B_DIM + b) * E_DIM + colbase + c4;
            split_store(kh, kl, r * FPITCH + c4, *(const float4*)(g_k + off));
            split_store(vh, vl, r * FPITCH + c4, *(const float4*)(g_v + off));
        }
        __syncthreads();

        // ---- S = Q @ K^T ----
        float s[8][4];
#pragma unroll
        for (int i = 0; i < 8; i++)
#pragma unroll
            for (int j = 0; j < 4; j++) s[i][j] = 0.f;

#pragma unroll
        for (int kb = 0; kb < 4; ++kb) {
            uint32_t a0[4], a1[4];
            int aoe = qOff + kb * 16;
            LDSM4(a0[0], a0[1], a0[2], a0[3], qhB + aoe * 2);
            LDSM4(a1[0], a1[1], a1[2], a1[3], qlB + aoe * 2);
#pragma unroll
            for (int np = 0; np < 4; ++np) {
                uint32_t bh[4], bl[4];
                int boe = kOff + np * 16 * FPITCH + kb * 16;
                LDSM4(bh[0], bh[1], bh[2], bh[3], khB + boe * 2);
                LDSM4(bl[0], bl[1], bl[2], bl[3], klB + boe * 2);
                MMA_BF16(s[2 * np], a0, bh[0], bh[1]);
                MMA_BF16(s[2 * np], a0, bl[0], bl[1]);
                MMA_BF16(s[2 * np], a1, bh[0], bh[1]);
                MMA_BF16(s[2 * np + 1], a0, bh[2], bh[3]);
                MMA_BF16(s[2 * np + 1], a0, bl[2], bl[3]);
                MMA_BF16(s[2 * np + 1], a1, bh[2], bh[3]);
            }
        }

        // ---- causal mask (only near-diagonal tiles) ----
        if (j0 + 63 > i0 + w * 16) {
#pragma unroll
            for (int nf = 0; nf < 8; ++nf) {
                int j = j0 + nf * 8 + ((lane & 3) << 1);
                if (j     > rg0)     s[nf][0] = -1e9f;
                if (j + 1 > rg0)     s[nf][1] = -1e9f;
                if (j     > rg0 + 8) s[nf][2] = -1e9f;
                if (j + 1 > rg0 + 8) s[nf][3] = -1e9f;
            }
        }

        // ---- online softmax (per row-half; stats shared across quad lanes) ----
#pragma unroll
        for (int half = 0; half < 2; ++half) {
            const int e0 = half * 2, e1 = half * 2 + 1;
            float vmax = -1e9f;
#pragma unroll
            for (int nf = 0; nf < 8; ++nf)
                vmax = fmaxf(vmax, fmaxf(s[nf][e0], s[nf][e1]));
            vmax = fmaxf(vmax, __shfl_xor_sync(0xffffffffu, vmax, 1));
            vmax = fmaxf(vmax, __shfl_xor_sync(0xffffffffu, vmax, 2));
            float mnew = fmaxf(s_m[half], vmax);
            float corr = fast_exp(s_m[half] - mnew);
            float rsum = 0.f;
#pragma unroll
            for (int nf = 0; nf < 8; ++nf) {
                s[nf][e0] = fast_exp(s[nf][e0] - mnew);
                s[nf][e1] = fast_exp(s[nf][e1] - mnew);
                rsum += s[nf][e0] + s[nf][e1];
            }
            rsum += __shfl_xor_sync(0xffffffffu, rsum, 1);
            rsum += __shfl_xor_sync(0xffffffffu, rsum, 2);
            s_l[half] = s_l[half] * corr + rsum;
            s_m[half] = mnew;
#pragma unroll
            for (int nf = 0; nf < 8; ++nf) {
                o[nf][e0] *= corr;
                o[nf][e1] *= corr;
            }
        }

        // ---- O += P @ V ----
#pragma unroll
        for (int kc = 0; kc < 4; ++kc) {
            uint32_t ph[4], pl[4];
            split_pack(s[2 * kc][0],     s[2 * kc][1],     ph[0], pl[0]);
            split_pack(s[2 * kc][2],     s[2 * kc][3],     ph[1], pl[1]);
            split_pack(s[2 * kc + 1][0], s[2 * kc + 1][1], ph[2], pl[2]);
            split_pack(s[2 * kc + 1][2], s[2 * kc + 1][3], ph[3], pl[3]);
#pragma unroll
            for (int np = 0; np < 4; ++np) {
                uint32_t bh[4], bl[4];
                int voe = vOff + kc * 16 * FPITCH + np * 16;
                LDSM4T(bh[0], bh[1], bh[2], bh[3], vhB + voe * 2);
                LDSM4T(bl[0], bl[1], bl[2], bl[3], vlB + voe * 2);
                MMA_BF16(o[2 * np], ph, bh[0], bh[1]);
                MMA_BF16(o[2 * np], ph, bl[0], bl[1]);
                MMA_BF16(o[2 * np], pl, bh[0], bh[1]);
                MMA_BF16(o[2 * np + 1], ph, bh[2], bh[3]);
                MMA_BF16(o[2 * np + 1], ph, bl[2], bl[3]);
                MMA_BF16(o[2 * np + 1], pl, bh[2], bh[3]);
            }
        }
    }

    // ---- finalize ----
    const float inv0 = 1.f / s_l[0];
    const float inv1 = 1.f / s_l[1];
#pragma unroll
    for (int nf = 0; nf < 8; ++nf) {
        size_t col = colbase + nf * 8 + ((lane & 3) << 1);
        float2 v0 = make_float2(o[nf][0] * inv0, o[nf][1] * inv0);
        float2 v1 = make_float2(o[nf][2] * inv1, o[nf][3] * inv1);
        *(float2*)(g_attn + ((size_t)rg0 * B_DIM + b) * E_DIM + col)       = v0;
        *(float2*)(g_attn + ((size_t)(rg0 + 8) * B_DIM + b) * E_DIM + col) = v1;
    }
}

// ===========================================================================
// kernel_launch
// Inputs: query, Wq, bq, Wk, bk, Wv, bv, Wo, bo, attn_mask (ignored: causal)
// ===========================================================================
extern "C" void kernel_launch(void* const* d_in, const int* in_sizes, int n_in,
                              void* d_out, int out_size)
{
    const float* query = (const float*)d_in[0];
    const float* Wq    = (const float*)d_in[1];
    const float* bq    = (const float*)d_in[2];
    const float* Wk    = (const float*)d_in[3];
    const float* bk    = (const float*)d_in[4];
    const float* Wv    = (const float*)d_in[5];
    const float* bv    = (const float*)d_in[6];
    const float* Wo    = (const float*)d_in[7];
    const float* bo    = (const float*)d_in[8];
    float* out = (float*)d_out;

    const int flash_smem = FSM_ELEMS * (int)sizeof(uint16_t);   // 73728
    cudaFuncSetAttribute(flash_mma_kernel, cudaFuncAttributeMaxDynamicSharedMemorySize, flash_smem);

    // QKV projections (z selects Q/K/V)
    qkv_kernel<<<dim3(E_DIM / 128, MROWS / 128, 3), 256>>>(query, Wq, bq, Wk, bk, Wv, bv);

    // causal flash attention: 16 q-tiles x 32 heads
    flash_mma_kernel<<<dim3(T_DIM / 128, B_DIM * H_DIM), 256, flash_smem>>>();

    // output projection
    oproj_kernel<<<dim3(E_DIM / 128, MROWS / 128), 256>>>(Wo, bo, out);
}

// round 4
// speedup vs baseline: 2.8751x; 1.1833x over previous
#include <cuda_runtime.h>
#include <cuda_bf16.h>
#include <math.h>
#include <stdint.h>

// Problem constants
#define T_DIM 2048
#define B_DIM 2
#define E_DIM 1024
#define H_DIM 16
#define DH    64
#define MROWS (T_DIM * B_DIM)   // 4096
#define NELEM (MROWS * E_DIM)   // 4194304

// Scratch: split-bf16 operands (device globals — no allocation allowed)
__device__ __nv_bfloat16 gXh[NELEM], gXl[NELEM];           // input X split
__device__ __nv_bfloat16 gWh[NELEM], gWl[NELEM];           // Wq,Wk,Wv,Wo (1M each)
__device__ __nv_bfloat16 gQh[NELEM], gQl[NELEM];
__device__ __nv_bfloat16 gKh[NELEM], gKl[NELEM];
__device__ __nv_bfloat16 gVh[NELEM], gVl[NELEM];
__device__ __nv_bfloat16 gAh[NELEM], gAl[NELEM];           // attn output split

// ===========================================================================
// Helpers
// ===========================================================================
__device__ __forceinline__ uint32_t smem_u32(const void* p) {
    uint32_t a;
    asm("{ .reg .u64 t; cvta.to.shared.u64 t, %1; cvt.u32.u64 %0, t; }" : "=r"(a) : "l"(p));
    return a;
}

#define LDSM4(R0, R1, R2, R3, ADDR) \
    asm volatile("ldmatrix.sync.aligned.m8n8.x4.shared.b16 {%0,%1,%2,%3}, [%4];" \
                 : "=r"(R0), "=r"(R1), "=r"(R2), "=r"(R3) : "r"(ADDR))

#define LDSM4T(R0, R1, R2, R3, ADDR) \
    asm volatile("ldmatrix.sync.aligned.m8n8.x4.trans.shared.b16 {%0,%1,%2,%3}, [%4];" \
                 : "=r"(R0), "=r"(R1), "=r"(R2), "=r"(R3) : "r"(ADDR))

#define MMA_BF16(D, A, B0, B1) \
    asm volatile("mma.sync.aligned.m16n8k16.row.col.f32.bf16.bf16.f32 " \
                 "{%0,%1,%2,%3}, {%4,%5,%6,%7}, {%8,%9}, {%0,%1,%2,%3};" \
                 : "+f"((D)[0]), "+f"((D)[1]), "+f"((D)[2]), "+f"((D)[3]) \
                 : "r"((A)[0]), "r"((A)[1]), "r"((A)[2]), "r"((A)[3]), "r"(B0), "r"(B1))

#define CP_ASYNC16(DST, SRC) \
    asm volatile("cp.async.cg.shared.global [%0], [%1], 16;" :: "r"(DST), "l"(SRC) : "memory")
#define CP_COMMIT() asm volatile("cp.async.commit_group;" ::: "memory")
#define CP_WAIT(N)  asm volatile("cp.async.wait_group %0;" :: "n"(N) : "memory")

// pack two f32 into bf16x2 hi + residual lo
__device__ __forceinline__ void split_pack(float a, float b, uint32_t& hi, uint32_t& lo) {
    __nv_bfloat162 H, L;
    H.x = __float2bfloat16(a); H.y = __float2bfloat16(b);
    L.x = __float2bfloat16(a - __bfloat162float(H.x));
    L.y = __float2bfloat16(b - __bfloat162float(H.y));
    hi = *(uint32_t*)&H; lo = *(uint32_t*)&L;
}

// fast exp on FMA pipe (no MUFU)
__device__ __forceinline__ float fast_exp(float x) {
    float y = fmaxf(x * 1.44269504f, -126.0f);
    int   e = __float2int_rn(y);
    float f = y - (float)e;
    float p = 1.33336e-3f;
    p = fmaf(p, f, 9.61812e-3f);
    p = fmaf(p, f, 5.55041e-2f);
    p = fmaf(p, f, 2.402265e-1f);
    p = fmaf(p, f, 6.931472e-1f);
    p = fmaf(p, f, 1.0f);
    return __int_as_float((e + 127) << 23) * p;
}

// ===========================================================================
// Convert kernel: split X and the 4 weight matrices into hi/lo bf16 globals.
// 2,097,152 float4 work items.
// ===========================================================================
__global__ void __launch_bounds__(256)
convert_kernel(const float* __restrict__ X,
               const float* __restrict__ Wq, const float* __restrict__ Wk,
               const float* __restrict__ Wv, const float* __restrict__ Wo)
{
    int i = blockIdx.x * 256 + threadIdx.x;       // 0 .. 2097151
    const float4* src;
    __nv_bfloat16 *dh, *dl;
    int off;
    if (i < 1048576) {
        src = (const float4*)X; dh = gXh; dl = gXl; off = i;
    } else {
        int j = i - 1048576;
        int r = j >> 18;                           // 0..3 -> Wq,Wk,Wv,Wo
        off = j & 0x3FFFF;
        src = (const float4*)(r == 0 ? Wq : r == 1 ? Wk : r == 2 ? Wv : Wo);
        dh = gWh + ((size_t)r << 20);
        dl = gWl + ((size_t)r << 20);
    }
    float4 v = src[off];
    uint32_t h01, l01, h23, l23;
    split_pack(v.x, v.y, h01, l01);
    split_pack(v.z, v.w, h23, l23);
    uint2 hw = make_uint2(h01, h23);
    uint2 lw = make_uint2(l01, l23);
    *(uint2*)(dh + (size_t)off * 4) = hw;
    *(uint2*)(dl + (size_t)off * 4) = lw;
}

// ===========================================================================
// GEMM on tensor cores: C = (A @ W^T + bias) * alpha, split-bf16 operands.
// CTA 128x128, 8 warps (2x4), BK=32, 4-stage cp.async pipeline.
// Smem pitch 40 bf16 (80B) -> conflict-free ldmatrix, 16B-aligned cp.async.
// MODE 0: write f32 to Cf.  MODE 1: write split bf16 to Ch/Cl.
// ===========================================================================
#define GPITCH 40
#define GARR_E (128 * GPITCH)          // 5120 elems per array
#define GSTAGE_E (4 * GARR_E)          // 20480 elems per stage
#define GS 4
#define GSMEM_BYTES (GS * GSTAGE_E * 2)  // 163840

__device__ __forceinline__ void gemm_produce(
    uint32_t smb, int stage,
    const __nv_bfloat16* __restrict__ Ah, const __nv_bfloat16* __restrict__ Al,
    const __nv_bfloat16* __restrict__ Bh, const __nv_bfloat16* __restrict__ Bl,
    int row0, int col0, int k0, int tid)
{
#pragma unroll
    for (int i = 0; i < 8; ++i) {
        int id  = tid + i * 256;         // 0..2047
        int arr = id >> 9;               // 0:Ah 1:Al 2:Bh 3:Bl
        int rid = (id >> 2) & 127;
        int cc  = id & 3;
        const __nv_bfloat16* g = (arr == 0) ? Ah : (arr == 1) ? Al : (arr == 2) ? Bh : Bl;
        int grow = ((arr < 2) ? row0 : col0) + rid;
        const __nv_bfloat16* src = g + (size_t)grow * E_DIM + k0 + cc * 8;
        uint32_t dst = smb + (uint32_t)(stage * GSTAGE_E + arr * GARR_E + rid * GPITCH + cc * 8) * 2;
        CP_ASYNC16(dst, src);
    }
}

template <int MODE>
__device__ __forceinline__ void gemm_cp(
    const __nv_bfloat16* __restrict__ Ah, const __nv_bfloat16* __restrict__ Al,
    const __nv_bfloat16* __restrict__ Bh, const __nv_bfloat16* __restrict__ Bl,
    const float* __restrict__ bias, float alpha,
    float* __restrict__ Cf,
    __nv_bfloat16* __restrict__ Ch, __nv_bfloat16* __restrict__ Cl)
{
    extern __shared__ char dynsm[];
    const uint32_t smb = smem_u32(dynsm);
    const int tid  = threadIdx.x;
    const int lane = tid & 31;
    const int wid  = tid >> 5;
    const int wy   = wid >> 2;
    const int wx   = wid & 3;
    const int row0 = blockIdx.y * 128;
    const int col0 = blockIdx.x * 128;

    const int aOffE = (wy * 64 + (lane & 15)) * GPITCH + ((lane >> 4) & 1) * 8;
    const int bOffE = (wx * 32 + (lane & 7) + ((lane >> 4) & 1) * 8) * GPITCH + ((lane >> 3) & 1) * 8;

    float acc[4][4][4];
#pragma unroll
    for (int i = 0; i < 4; i++)
#pragma unroll
        for (int j = 0; j < 4; j++)
#pragma unroll
            for (int k = 0; k < 4; k++) acc[i][j][k] = 0.f;

    // prologue: stages 0..2 <- chunks 0..2
#pragma unroll
    for (int s = 0; s < GS - 1; ++s) {
        gemm_produce(smb, s, Ah, Al, Bh, Bl, row0, col0, s * 32, tid);
        CP_COMMIT();
    }

    for (int c = 0; c < 32; ++c) {
        CP_WAIT(GS - 2);
        __syncthreads();

        // prefetch chunk c+3 (wrap-around keeps group count uniform; tail
        // wraps into stages that are never read again)
        gemm_produce(smb, (c + GS - 1) & (GS - 1), Ah, Al, Bh, Bl,
                     row0, col0, ((c + GS - 1) & 31) * 32, tid);
        CP_COMMIT();

        const uint32_t stA = smb + (uint32_t)((c & (GS - 1)) * GSTAGE_E) * 2;
        const uint32_t aHb = stA;
        const uint32_t aLb = stA + GARR_E * 2;
        const uint32_t bHb = stA + 2 * GARR_E * 2;
        const uint32_t bLb = stA + 3 * GARR_E * 2;

#pragma unroll
        for (int kb = 0; kb < 2; ++kb) {
            uint32_t bh[4][2], bl[4][2];
#pragma unroll
            for (int np = 0; np < 2; ++np) {
                int boe = bOffE + np * 16 * GPITCH + kb * 16;
                LDSM4(bh[2 * np][0], bh[2 * np][1], bh[2 * np + 1][0], bh[2 * np + 1][1],
                      bHb + boe * 2);
                LDSM4(bl[2 * np][0], bl[2 * np][1], bl[2 * np + 1][0], bl[2 * np + 1][1],
                      bLb + boe * 2);
            }
#pragma unroll
            for (int mf = 0; mf < 4; ++mf) {
                uint32_t ah[4], al[4];
                int aoe = aOffE + mf * 16 * GPITCH + kb * 16;
                LDSM4(ah[0], ah[1], ah[2], ah[3], aHb + aoe * 2);
                LDSM4(al[0], al[1], al[2], al[3], aLb + aoe * 2);
#pragma unroll
                for (int nf = 0; nf < 4; ++nf) {
                    MMA_BF16(acc[mf][nf], ah, bh[nf][0], bh[nf][1]);
                    MMA_BF16(acc[mf][nf], ah, bl[nf][0], bl[nf][1]);
                    MMA_BF16(acc[mf][nf], al, bh[nf][0], bh[nf][1]);
                }
            }
        }
    }

    // epilogue
#pragma unroll
    for (int mf = 0; mf < 4; ++mf) {
        int r = row0 + wy * 64 + mf * 16 + (lane >> 2);
#pragma unroll
        for (int nf = 0; nf < 4; ++nf) {
            int col = col0 + wx * 32 + nf * 8 + ((lane & 3) << 1);
            float b0 = bias[col], b1 = bias[col + 1];
            float v0 = (acc[mf][nf][0] + b0) * alpha;
            float v1 = (acc[mf][nf][1] + b1) * alpha;
            float v2 = (acc[mf][nf][2] + b0) * alpha;
            float v3 = (acc[mf][nf][3] + b1) * alpha;
            if (MODE == 0) {
                *(float2*)(Cf + (size_t)r * E_DIM + col)       = make_float2(v0, v1);
                *(float2*)(Cf + (size_t)(r + 8) * E_DIM + col) = make_float2(v2, v3);
            } else {
                uint32_t h01, l01, h23, l23;
                split_pack(v0, v1, h01, l01);
                split_pack(v2, v3, h23, l23);
                *(uint32_t*)(Ch + (size_t)r * E_DIM + col)       = h01;
                *(uint32_t*)(Cl + (size_t)r * E_DIM + col)       = l01;
                *(uint32_t*)(Ch + (size_t)(r + 8) * E_DIM + col) = h23;
                *(uint32_t*)(Cl + (size_t)(r + 8) * E_DIM + col) = l23;
            }
        }
    }
}

__global__ void __launch_bounds__(256)
qkv_kernel(const float* __restrict__ bq, const float* __restrict__ bk,
           const float* __restrict__ bv)
{
    const int z = blockIdx.z;
    const __nv_bfloat16* Bh = gWh + ((size_t)z << 20);
    const __nv_bfloat16* Bl = gWl + ((size_t)z << 20);
    if (z == 0)      gemm_cp<1>(gXh, gXl, Bh, Bl, bq, 0.125f, nullptr, gQh, gQl);
    else if (z == 1) gemm_cp<1>(gXh, gXl, Bh, Bl, bk, 1.0f,   nullptr, gKh, gKl);
    else             gemm_cp<1>(gXh, gXl, Bh, Bl, bv, 1.0f,   nullptr, gVh, gVl);
}

__global__ void __launch_bounds__(256)
oproj_kernel(const float* __restrict__ bo, float* __restrict__ out)
{
    gemm_cp<0>(gAh, gAl, gWh + ((size_t)3 << 20), gWl + ((size_t)3 << 20),
               bo, 1.0f, out, nullptr, nullptr);
}

// ===========================================================================
// Flash attention on tensor cores (causal), split-bf16 inputs via cp.async.
// BR=128 (8 warps x m16), BC=64, Dh=64. Double-buffered K/V tiles.
// Smem (bf16, pitch 72): Qh/Ql [128x64] + 2 stages of Kh/Kl/Vh/Vl [64x64].
// ===========================================================================
#define FPITCH 72
#define FQ_E   (128 * FPITCH)              // 9216 per Q array
#define FKV_E  (64 * FPITCH)               // 4608 per KV array
#define FSTAGE_E (4 * FKV_E)               // 18432 per stage
#define FKV0_E (2 * FQ_E)                  // 18432 (stage area starts here)
#define FSMEM_BYTES ((FKV0_E + 2 * FSTAGE_E) * 2)   // 110592

__global__ void __launch_bounds__(256)
flash_mma_kernel()
{
    extern __shared__ char dynsm[];
    const uint32_t smb = smem_u32(dynsm);

    const int tid  = threadIdx.x;
    const int lane = tid & 31;
    const int w    = tid >> 5;
    const int qt   = blockIdx.x;          // 0..15
    const int head = blockIdx.y;          // 0..31
    const int b    = head >> 4;
    const int h    = head & 15;
    const int i0   = qt * 128;
    const int colbase = h * DH;

    const int qOffE = (w * 16 + (lane & 15)) * FPITCH + ((lane >> 4) & 1) * 8;
    const int kOffE = ((lane & 7) + ((lane >> 4) & 1) * 8) * FPITCH + ((lane >> 3) & 1) * 8;
    const int vOffE = ((lane & 7) + ((lane >> 3) & 1) * 8) * FPITCH + ((lane >> 4) & 1) * 8;

    const int ktmax = 2 * qt + 1;

    // prologue: Q tile (both splits) + KV stage 0 in one group
#pragma unroll
    for (int i = 0; i < 8; ++i) {
        int id  = tid + i * 256;          // 0..2047
        int arr = id >> 10;               // 0:Qh 1:Ql
        int rid = (id >> 3) & 127;
        int cc  = id & 7;
        const __nv_bfloat16* g = arr ? gQl : gQh;
        const __nv_bfloat16* src = g + ((size_t)(i0 + rid) * B_DIM + b) * E_DIM + colbase + cc * 8;
        uint32_t dst = smb + (uint32_t)(arr * FQ_E + rid * FPITCH + cc * 8) * 2;
        CP_ASYNC16(dst, src);
    }
#pragma unroll
    for (int i = 0; i < 8; ++i) {
        int id  = tid + i * 256;
        int arr = id >> 9;                // 0:Kh 1:Kl 2:Vh 3:Vl
        int rid = (id >> 3) & 63;
        int cc  = id & 7;
        const __nv_bfloat16* g = (arr == 0) ? gKh : (arr == 1) ? gKl : (arr == 2) ? gVh : gVl;
        const __nv_bfloat16* src = g + ((size_t)rid * B_DIM + b) * E_DIM + colbase + cc * 8;
        uint32_t dst = smb + (uint32_t)(FKV0_E + arr * FKV_E + rid * FPITCH + cc * 8) * 2;
        CP_ASYNC16(dst, src);
    }
    CP_COMMIT();

    float s_m[2] = {-1e9f, -1e9f};
    float s_l[2] = {0.f, 0.f};
    float o[8][4];
#pragma unroll
    for (int i = 0; i < 8; i++)
#pragma unroll
        for (int j = 0; j < 4; j++) o[i][j] = 0.f;

    const int rg0 = i0 + w * 16 + (lane >> 2);
    const uint32_t qhB = smb;
    const uint32_t qlB = smb + FQ_E * 2;

    for (int kt = 0; kt <= ktmax; ++kt) {
        CP_WAIT(0);
        __syncthreads();

        // prefetch next KV tile (clamped; tail re-load lands in unused stage)
        {
            int ktn = (kt + 1 <= ktmax) ? (kt + 1) : ktmax;
            int j0n = ktn * 64;
            int stn = (kt + 1) & 1;
#pragma unroll
            for (int i = 0; i < 8; ++i) {
                int id  = tid + i * 256;
                int arr = id >> 9;
                int rid = (id >> 3) & 63;
                int cc  = id & 7;
                const __nv_bfloat16* g = (arr == 0) ? gKh : (arr == 1) ? gKl : (arr == 2) ? gVh : gVl;
                const __nv_bfloat16* src = g + ((size_t)(j0n + rid) * B_DIM + b) * E_DIM + colbase + cc * 8;
                uint32_t dst = smb + (uint32_t)(FKV0_E + stn * FSTAGE_E + arr * FKV_E + rid * FPITCH + cc * 8) * 2;
                CP_ASYNC16(dst, src);
            }
            CP_COMMIT();
        }

        const int j0 = kt * 64;
        const uint32_t stKV = smb + (uint32_t)(FKV0_E + (kt & 1) * FSTAGE_E) * 2;
        const uint32_t khB = stKV;
        const uint32_t klB = stKV + FKV_E * 2;
        const uint32_t vhB = stKV + 2 * FKV_E * 2;
        const uint32_t vlB = stKV + 3 * FKV_E * 2;

        // ---- S = Q @ K^T ----
        float s[8][4];
#pragma unroll
        for (int i = 0; i < 8; i++)
#pragma unroll
            for (int j = 0; j < 4; j++) s[i][j] = 0.f;

#pragma unroll
        for (int kb = 0; kb < 4; ++kb) {
            uint32_t a0[4], a1[4];
            int aoe = qOffE + kb * 16;
            LDSM4(a0[0], a0[1], a0[2], a0[3], qhB + aoe * 2);
            LDSM4(a1[0], a1[1], a1[2], a1[3], qlB + aoe * 2);
#pragma unroll
            for (int np = 0; np < 4; ++np) {
                uint32_t bh[4], bl[4];
                int boe = kOffE + np * 16 * FPITCH + kb * 16;
                LDSM4(bh[0], bh[1], bh[2], bh[3], khB + boe * 2);
                LDSM4(bl[0], bl[1], bl[2], bl[3], klB + boe * 2);
                MMA_BF16(s[2 * np], a0, bh[0], bh[1]);
                MMA_BF16(s[2 * np], a0, bl[0], bl[1]);
                MMA_BF16(s[2 * np], a1, bh[0], bh[1]);
                MMA_BF16(s[2 * np + 1], a0, bh[2], bh[3]);
                MMA_BF16(s[2 * np + 1], a0, bl[2], bl[3]);
                MMA_BF16(s[2 * np + 1], a1, bh[2], bh[3]);
            }
        }

        // ---- causal mask ----
        if (j0 + 63 > i0 + w * 16) {
#pragma unroll
            for (int nf = 0; nf < 8; ++nf) {
                int j = j0 + nf * 8 + ((lane & 3) << 1);
                if (j     > rg0)     s[nf][0] = -1e9f;
                if (j + 1 > rg0)     s[nf][1] = -1e9f;
                if (j     > rg0 + 8) s[nf][2] = -1e9f;
                if (j + 1 > rg0 + 8) s[nf][3] = -1e9f;
            }
        }

        // ---- online softmax ----
#pragma unroll
        for (int half = 0; half < 2; ++half) {
            const int e0 = half * 2, e1 = half * 2 + 1;
            float vmax = -1e9f;
#pragma unroll
            for (int nf = 0; nf < 8; ++nf)
                vmax = fmaxf(vmax, fmaxf(s[nf][e0], s[nf][e1]));
            vmax = fmaxf(vmax, __shfl_xor_sync(0xffffffffu, vmax, 1));
            vmax = fmaxf(vmax, __shfl_xor_sync(0xffffffffu, vmax, 2));
            float mnew = fmaxf(s_m[half], vmax);
            float corr = fast_exp(s_m[half] - mnew);
            float rsum = 0.f;
#pragma unroll
            for (int nf = 0; nf < 8; ++nf) {
                s[nf][e0] = fast_exp(s[nf][e0] - mnew);
                s[nf][e1] = fast_exp(s[nf][e1] - mnew);
                rsum += s[nf][e0] + s[nf][e1];
            }
            rsum += __shfl_xor_sync(0xffffffffu, rsum, 1);
            rsum += __shfl_xor_sync(0xffffffffu, rsum, 2);
            s_l[half] = s_l[half] * corr + rsum;
            s_m[half] = mnew;
#pragma unroll
            for (int nf = 0; nf < 8; ++nf) {
                o[nf][e0] *= corr;
                o[nf][e1] *= corr;
            }
        }

        // ---- O += P @ V ----
#pragma unroll
        for (int kc = 0; kc < 4; ++kc) {
            uint32_t ph[4], pl[4];
            split_pack(s[2 * kc][0],     s[2 * kc][1],     ph[0], pl[0]);
            split_pack(s[2 * kc][2],     s[2 * kc][3],     ph[1], pl[1]);
            split_pack(s[2 * kc + 1][0], s[2 * kc + 1][1], ph[2], pl[2]);
            split_pack(s[2 * kc + 1][2], s[2 * kc + 1][3], ph[3], pl[3]);
#pragma unroll
            for (int np = 0; np < 4; ++np) {
                uint32_t bh[4], bl[4];
                int voe = vOffE + kc * 16 * FPITCH + np * 16;
                LDSM4T(bh[0], bh[1], bh[2], bh[3], vhB + voe * 2);
                LDSM4T(bl[0], bl[1], bl[2], bl[3], vlB + voe * 2);
                MMA_BF16(o[2 * np], ph, bh[0], bh[1]);
                MMA_BF16(o[2 * np], ph, bl[0], bl[1]);
                MMA_BF16(o[2 * np], pl, bh[0], bh[1]);
                MMA_BF16(o[2 * np + 1], ph, bh[2], bh[3]);
                MMA_BF16(o[2 * np + 1], ph, bl[2], bl[3]);
                MMA_BF16(o[2 * np + 1], pl, bh[2], bh[3]);
            }
        }
        __syncthreads();
    }

    // ---- finalize: write split-bf16 attn for the O-projection ----
    const float inv0 = 1.f / s_l[0];
    const float inv1 = 1.f / s_l[1];
#pragma unroll
    for (int nf = 0; nf < 8; ++nf) {
        int col = colbase + nf * 8 + ((lane & 3) << 1);
        float v0 = o[nf][0] * inv0, v1 = o[nf][1] * inv0;
        float v2 = o[nf][2] * inv1, v3 = o[nf][3] * inv1;
        uint32_t h01, l01, h23, l23;
        split_pack(v0, v1, h01, l01);
        split_pack(v2, v3, h23, l23);
        size_t r0off = ((size_t)rg0 * B_DIM + b) * E_DIM + col;
        size_t r1off = ((size_t)(rg0 + 8) * B_DIM + b) * E_DIM + col;
        *(uint32_t*)(gAh + r0off) = h01;
        *(uint32_t*)(gAl + r0off) = l01;
        *(uint32_t*)(gAh + r1off) = h23;
        *(uint32_t*)(gAl + r1off) = l23;
    }
}

// ===========================================================================
// kernel_launch
// Inputs: query, Wq, bq, Wk, bk, Wv, bv, Wo, bo, attn_mask (ignored: causal)
// ===========================================================================
extern "C" void kernel_launch(void* const* d_in, const int* in_sizes, int n_in,
                              void* d_out, int out_size)
{
    const float* query = (const float*)d_in[0];
    const float* Wq    = (const float*)d_in[1];
    const float* bq    = (const float*)d_in[2];
    const float* Wk    = (const float*)d_in[3];
    const float* bk    = (const float*)d_in[4];
    const float* Wv    = (const float*)d_in[5];
    const float* bv    = (const float*)d_in[6];
    const float* Wo    = (const float*)d_in[7];
    const float* bo    = (const float*)d_in[8];
    float* out = (float*)d_out;

    cudaFuncSetAttribute(qkv_kernel, cudaFuncAttributeMaxDynamicSharedMemorySize, GSMEM_BYTES);
    cudaFuncSetAttribute(oproj_kernel, cudaFuncAttributeMaxDynamicSharedMemorySize, GSMEM_BYTES);
    cudaFuncSetAttribute(flash_mma_kernel, cudaFuncAttributeMaxDynamicSharedMemorySize, FSMEM_BYTES);

    // split X and weights to bf16 hi/lo
    convert_kernel<<<8192, 256>>>(query, Wq, Wk, Wv, Wo);

    // QKV projections (z selects Q/K/V), outputs split bf16
    qkv_kernel<<<dim3(E_DIM / 128, MROWS / 128, 3), 256, GSMEM_BYTES>>>(bq, bk, bv);

    // causal flash attention
    flash_mma_kernel<<<dim3(T_DIM / 128, B_DIM * H_DIM), 256, FSMEM_BYTES>>>();

    // output projection -> f32 out
    oproj_kernel<<<dim3(E_DIM / 128, MROWS / 128), 256, GSMEM_BYTES>>>(bo, out);
}

// round 5
// speedup vs baseline: 3.4378x; 1.1957x over previous
#include <cuda_runtime.h>
#include <cuda_bf16.h>
#include <math.h>
#include <stdint.h>

// Problem constants
#define T_DIM 2048
#define B_DIM 2
#define E_DIM 1024
#define H_DIM 16
#define DH    64
#define MROWS (T_DIM * B_DIM)   // 4096
#define NELEM (MROWS * E_DIM)   // 4194304

// Scratch: split-bf16 operands (device globals — no allocation allowed)
__device__ __nv_bfloat16 gXh[NELEM], gXl[NELEM];           // input X split
__device__ __nv_bfloat16 gWh[NELEM], gWl[NELEM];           // Wq,Wk,Wv,Wo (1M each)
__device__ __nv_bfloat16 gQh[NELEM], gQl[NELEM];
__device__ __nv_bfloat16 gKh[NELEM], gKl[NELEM];
__device__ __nv_bfloat16 gVh[NELEM], gVl[NELEM];
__device__ __nv_bfloat16 gAh[NELEM], gAl[NELEM];           // attn output split

// ===========================================================================
// Helpers
// ===========================================================================
__device__ __forceinline__ uint32_t smem_u32(const void* p) {
    uint32_t a;
    asm("{ .reg .u64 t; cvta.to.shared.u64 t, %1; cvt.u32.u64 %0, t; }" : "=r"(a) : "l"(p));
    return a;
}

#define LDSM4(R0, R1, R2, R3, ADDR) \
    asm volatile("ldmatrix.sync.aligned.m8n8.x4.shared.b16 {%0,%1,%2,%3}, [%4];" \
                 : "=r"(R0), "=r"(R1), "=r"(R2), "=r"(R3) : "r"(ADDR))

#define LDSM4T(R0, R1, R2, R3, ADDR) \
    asm volatile("ldmatrix.sync.aligned.m8n8.x4.trans.shared.b16 {%0,%1,%2,%3}, [%4];" \
                 : "=r"(R0), "=r"(R1), "=r"(R2), "=r"(R3) : "r"(ADDR))

#define MMA_BF16(D, A, B0, B1) \
    asm volatile("mma.sync.aligned.m16n8k16.row.col.f32.bf16.bf16.f32 " \
                 "{%0,%1,%2,%3}, {%4,%5,%6,%7}, {%8,%9}, {%0,%1,%2,%3};" \
                 : "+f"((D)[0]), "+f"((D)[1]), "+f"((D)[2]), "+f"((D)[3]) \
                 : "r"((A)[0]), "r"((A)[1]), "r"((A)[2]), "r"((A)[3]), "r"(B0), "r"(B1))

#define CP_ASYNC16(DST, SRC) \
    asm volatile("cp.async.cg.shared.global [%0], [%1], 16;" :: "r"(DST), "l"(SRC) : "memory")
#define CP_COMMIT() asm volatile("cp.async.commit_group;" ::: "memory")
#define CP_WAIT(N)  asm volatile("cp.async.wait_group %0;" :: "n"(N) : "memory")

// pack two f32 into bf16x2 hi + residual lo
__device__ __forceinline__ void split_pack(float a, float b, uint32_t& hi, uint32_t& lo) {
    __nv_bfloat162 H, L;
    H.x = __float2bfloat16(a); H.y = __float2bfloat16(b);
    L.x = __float2bfloat16(a - __bfloat162float(H.x));
    L.y = __float2bfloat16(b - __bfloat162float(H.y));
    hi = *(uint32_t*)&H; lo = *(uint32_t*)&L;
}

// fast exp on FMA pipe (no MUFU)
__device__ __forceinline__ float fast_exp(float x) {
    float y = fmaxf(x * 1.44269504f, -126.0f);
    int   e = __float2int_rn(y);
    float f = y - (float)e;
    float p = 1.33336e-3f;
    p = fmaf(p, f, 9.61812e-3f);
    p = fmaf(p, f, 5.55041e-2f);
    p = fmaf(p, f, 2.402265e-1f);
    p = fmaf(p, f, 6.931472e-1f);
    p = fmaf(p, f, 1.0f);
    return __int_as_float((e + 127) << 23) * p;
}

// ===========================================================================
// Convert kernel: split X and the 4 weight matrices into hi/lo bf16 globals.
// ===========================================================================
__global__ void __launch_bounds__(256)
convert_kernel(const float* __restrict__ X,
               const float* __restrict__ Wq, const float* __restrict__ Wk,
               const float* __restrict__ Wv, const float* __restrict__ Wo)
{
    int i = blockIdx.x * 256 + threadIdx.x;       // 0 .. 2097151
    const float4* src;
    __nv_bfloat16 *dh, *dl;
    int off;
    if (i < 1048576) {
        src = (const float4*)X; dh = gXh; dl = gXl; off = i;
    } else {
        int j = i - 1048576;
        int r = j >> 18;                           // 0..3 -> Wq,Wk,Wv,Wo
        off = j & 0x3FFFF;
        src = (const float4*)(r == 0 ? Wq : r == 1 ? Wk : r == 2 ? Wv : Wo);
        dh = gWh + ((size_t)r << 20);
        dl = gWl + ((size_t)r << 20);
    }
    float4 v = src[off];
    uint32_t h01, l01, h23, l23;
    split_pack(v.x, v.y, h01, l01);
    split_pack(v.z, v.w, h23, l23);
    *(uint2*)(dh + (size_t)off * 4) = make_uint2(h01, h23);
    *(uint2*)(dl + (size_t)off * 4) = make_uint2(l01, l23);
}

// ===========================================================================
// GEMM on tensor cores: C = (A @ W^T + bias) * alpha, split-bf16 operands.
// CTA 128x128, 8 warps (2x4), BK=32, 2-stage cp.async pipeline, 2 CTAs/SM.
// ===========================================================================
#define GPITCH 40
#define GARR_E (128 * GPITCH)          // 5120 elems per array
#define GSTAGE_E (4 * GARR_E)          // 20480 elems per stage
#define GS 2
#define GSMEM_BYTES (GS * GSTAGE_E * 2)  // 81920

__device__ __forceinline__ void gemm_produce(
    uint32_t smb, int stage,
    const __nv_bfloat16* __restrict__ Ah, const __nv_bfloat16* __restrict__ Al,
    const __nv_bfloat16* __restrict__ Bh, const __nv_bfloat16* __restrict__ Bl,
    int row0, int col0, int k0, int tid)
{
#pragma unroll
    for (int i = 0; i < 8; ++i) {
        int id  = tid + i * 256;         // 0..2047
        int arr = id >> 9;               // 0:Ah 1:Al 2:Bh 3:Bl
        int rid = (id >> 2) & 127;
        int cc  = id & 3;
        const __nv_bfloat16* g = (arr == 0) ? Ah : (arr == 1) ? Al : (arr == 2) ? Bh : Bl;
        int grow = ((arr < 2) ? row0 : col0) + rid;
        const __nv_bfloat16* src = g + (size_t)grow * E_DIM + k0 + cc * 8;
        uint32_t dst = smb + (uint32_t)(stage * GSTAGE_E + arr * GARR_E + rid * GPITCH + cc * 8) * 2;
        CP_ASYNC16(dst, src);
    }
}

template <int MODE>
__device__ __forceinline__ void gemm_cp(
    const __nv_bfloat16* __restrict__ Ah, const __nv_bfloat16* __restrict__ Al,
    const __nv_bfloat16* __restrict__ Bh, const __nv_bfloat16* __restrict__ Bl,
    const float* __restrict__ bias, float alpha,
    float* __restrict__ Cf,
    __nv_bfloat16* __restrict__ Ch, __nv_bfloat16* __restrict__ Cl)
{
    extern __shared__ char dynsm[];
    const uint32_t smb = smem_u32(dynsm);
    const int tid  = threadIdx.x;
    const int lane = tid & 31;
    const int wid  = tid >> 5;
    const int wy   = wid >> 2;
    const int wx   = wid & 3;
    const int row0 = blockIdx.y * 128;
    const int col0 = blockIdx.x * 128;

    const int aOffE = (wy * 64 + (lane & 15)) * GPITCH + ((lane >> 4) & 1) * 8;
    const int bOffE = (wx * 32 + (lane & 7) + ((lane >> 4) & 1) * 8) * GPITCH + ((lane >> 3) & 1) * 8;

    float acc[4][4][4];
#pragma unroll
    for (int i = 0; i < 4; i++)
#pragma unroll
        for (int j = 0; j < 4; j++)
#pragma unroll
            for (int k = 0; k < 4; k++) acc[i][j][k] = 0.f;

    // prologue: stage 0 <- chunk 0
    gemm_produce(smb, 0, Ah, Al, Bh, Bl, row0, col0, 0, tid);
    CP_COMMIT();

    for (int c = 0; c < 32; ++c) {
        // prefetch chunk c+1 into the other stage (safe: that stage's readers
        // finished at the end-of-iteration barrier of iter c-1)
        if (c + 1 < 32) {
            gemm_produce(smb, (c + 1) & 1, Ah, Al, Bh, Bl, row0, col0, (c + 1) * 32, tid);
            CP_COMMIT();
            CP_WAIT(1);
        } else {
            CP_WAIT(0);
        }
        __syncthreads();

        const uint32_t stA = smb + (uint32_t)((c & 1) * GSTAGE_E) * 2;
        const uint32_t aHb = stA;
        const uint32_t aLb = stA + GARR_E * 2;
        const uint32_t bHb = stA + 2 * GARR_E * 2;
        const uint32_t bLb = stA + 3 * GARR_E * 2;

#pragma unroll
        for (int kb = 0; kb < 2; ++kb) {
            uint32_t bh[4][2], bl[4][2];
#pragma unroll
            for (int np = 0; np < 2; ++np) {
                int boe = bOffE + np * 16 * GPITCH + kb * 16;
                LDSM4(bh[2 * np][0], bh[2 * np][1], bh[2 * np + 1][0], bh[2 * np + 1][1],
                      bHb + boe * 2);
                LDSM4(bl[2 * np][0], bl[2 * np][1], bl[2 * np + 1][0], bl[2 * np + 1][1],
                      bLb + boe * 2);
            }
#pragma unroll
            for (int mf = 0; mf < 4; ++mf) {
                uint32_t ah[4], al[4];
                int aoe = aOffE + mf * 16 * GPITCH + kb * 16;
                LDSM4(ah[0], ah[1], ah[2], ah[3], aHb + aoe * 2);
                LDSM4(al[0], al[1], al[2], al[3], aLb + aoe * 2);
#pragma unroll
                for (int nf = 0; nf < 4; ++nf) {
                    MMA_BF16(acc[mf][nf], ah, bh[nf][0], bh[nf][1]);
                    MMA_BF16(acc[mf][nf], ah, bl[nf][0], bl[nf][1]);
                    MMA_BF16(acc[mf][nf], al, bh[nf][0], bh[nf][1]);
                }
            }
        }
        __syncthreads();   // all reads of this stage done before it is refilled
    }

    // epilogue
#pragma unroll
    for (int mf = 0; mf < 4; ++mf) {
        int r = row0 + wy * 64 + mf * 16 + (lane >> 2);
#pragma unroll
        for (int nf = 0; nf < 4; ++nf) {
            int col = col0 + wx * 32 + nf * 8 + ((lane & 3) << 1);
            float b0 = bias[col], b1 = bias[col + 1];
            float v0 = (acc[mf][nf][0] + b0) * alpha;
            float v1 = (acc[mf][nf][1] + b1) * alpha;
            float v2 = (acc[mf][nf][2] + b0) * alpha;
            float v3 = (acc[mf][nf][3] + b1) * alpha;
            if (MODE == 0) {
                *(float2*)(Cf + (size_t)r * E_DIM + col)       = make_float2(v0, v1);
                *(float2*)(Cf + (size_t)(r + 8) * E_DIM + col) = make_float2(v2, v3);
            } else {
                uint32_t h01, l01, h23, l23;
                split_pack(v0, v1, h01, l01);
                split_pack(v2, v3, h23, l23);
                *(uint32_t*)(Ch + (size_t)r * E_DIM + col)       = h01;
                *(uint32_t*)(Cl + (size_t)r * E_DIM + col)       = l01;
                *(uint32_t*)(Ch + (size_t)(r + 8) * E_DIM + col) = h23;
                *(uint32_t*)(Cl + (size_t)(r + 8) * E_DIM + col) = l23;
            }
        }
    }
}

__global__ void __launch_bounds__(256, 2)
qkv_kernel(const float* __restrict__ bq, const float* __restrict__ bk,
           const float* __restrict__ bv)
{
    const int z = blockIdx.z;
    const __nv_bfloat16* Bh = gWh + ((size_t)z << 20);
    const __nv_bfloat16* Bl = gWl + ((size_t)z << 20);
    if (z == 0)      gemm_cp<1>(gXh, gXl, Bh, Bl, bq, 0.125f, nullptr, gQh, gQl);
    else if (z == 1) gemm_cp<1>(gXh, gXl, Bh, Bl, bk, 1.0f,   nullptr, gKh, gKl);
    else             gemm_cp<1>(gXh, gXl, Bh, Bl, bv, 1.0f,   nullptr, gVh, gVl);
}

__global__ void __launch_bounds__(256, 2)
oproj_kernel(const float* __restrict__ bo, float* __restrict__ out)
{
    gemm_cp<0>(gAh, gAl, gWh + ((size_t)3 << 20), gWl + ((size_t)3 << 20),
               bo, 1.0f, out, nullptr, nullptr);
}

// ===========================================================================
// Flash attention on tensor cores (causal), split-bf16 inputs via cp.async.
// BR=128 (8 warps x m16), BC=64, Dh=64. Double-buffered K/V tiles.
// Load-balanced: each CTA processes q-tile pair (p, 15-p) -> uniform 34 tiles.
// ===========================================================================
#define FPITCH 72
#define FQ_E   (128 * FPITCH)              // 9216 per Q array
#define FKV_E  (64 * FPITCH)               // 4608 per KV array
#define FSTAGE_E (4 * FKV_E)               // 18432 per stage
#define FKV0_E (2 * FQ_E)                  // 18432 (stage area starts here)
#define FSMEM_BYTES ((FKV0_E + 2 * FSTAGE_E) * 2)   // 110592

__device__ __forceinline__ void flash_kv_produce(uint32_t smb, int stage, int j0,
                                                 int b, int colbase, int tid)
{
#pragma unroll
    for (int i = 0; i < 8; ++i) {
        int id  = tid + i * 256;
        int arr = id >> 9;                // 0:Kh 1:Kl 2:Vh 3:Vl
        int rid = (id >> 3) & 63;
        int cc  = id & 7;
        const __nv_bfloat16* g = (arr == 0) ? gKh : (arr == 1) ? gKl : (arr == 2) ? gVh : gVl;
        const __nv_bfloat16* src = g + ((size_t)(j0 + rid) * B_DIM + b) * E_DIM + colbase + cc * 8;
        uint32_t dst = smb + (uint32_t)(FKV0_E + stage * FSTAGE_E + arr * FKV_E + rid * FPITCH + cc * 8) * 2;
        CP_ASYNC16(dst, src);
    }
}

__device__ __forceinline__ void flash_one(int qt, uint32_t smb, int b, int colbase,
                                          int tid, int lane, int w,
                                          int qOffE, int kOffE, int vOffE)
{
    const int i0 = qt * 128;
    const int ktmax = 2 * qt + 1;

    // prologue: Q tile (both splits) + KV stage 0 in one cp.async group
#pragma unroll
    for (int i = 0; i < 8; ++i) {
        int id  = tid + i * 256;          // 0..2047
        int arr = id >> 10;               // 0:Qh 1:Ql
        int rid = (id >> 3) & 127;
        int cc  = id & 7;
        const __nv_bfloat16* g = arr ? gQl : gQh;
        const __nv_bfloat16* src = g + ((size_t)(i0 + rid) * B_DIM + b) * E_DIM + colbase + cc * 8;
        uint32_t dst = smb + (uint32_t)(arr * FQ_E + rid * FPITCH + cc * 8) * 2;
        CP_ASYNC16(dst, src);
    }
    flash_kv_produce(smb, 0, 0, b, colbase, tid);
    CP_COMMIT();

    float s_m[2] = {-1e9f, -1e9f};
    float s_l[2] = {0.f, 0.f};
    float o[8][4];
#pragma unroll
    for (int i = 0; i < 8; i++)
#pragma unroll
        for (int j = 0; j < 4; j++) o[i][j] = 0.f;

    const int rg0 = i0 + w * 16 + (lane >> 2);
    const uint32_t qhB = smb;
    const uint32_t qlB = smb + FQ_E * 2;

    for (int kt = 0; kt <= ktmax; ++kt) {
        // prefetch next KV tile, keep it in flight while computing this one
        if (kt + 1 <= ktmax) {
            flash_kv_produce(smb, (kt + 1) & 1, (kt + 1) * 64, b, colbase, tid);
            CP_COMMIT();
            CP_WAIT(1);
        } else {
            CP_WAIT(0);
        }
        __syncthreads();

        const int j0 = kt * 64;
        const uint32_t stKV = smb + (uint32_t)(FKV0_E + (kt & 1) * FSTAGE_E) * 2;
        const uint32_t khB = stKV;
        const uint32_t klB = stKV + FKV_E * 2;
        const uint32_t vhB = stKV + 2 * FKV_E * 2;
        const uint32_t vlB = stKV + 3 * FKV_E * 2;

        // ---- S = Q @ K^T ----
        float s[8][4];
#pragma unroll
        for (int i = 0; i < 8; i++)
#pragma unroll
            for (int j = 0; j < 4; j++) s[i][j] = 0.f;

#pragma unroll
        for (int kb = 0; kb < 4; ++kb) {
            uint32_t a0[4], a1[4];
            int aoe = qOffE + kb * 16;
            LDSM4(a0[0], a0[1], a0[2], a0[3], qhB + aoe * 2);
            LDSM4(a1[0], a1[1], a1[2], a1[3], qlB + aoe * 2);
#pragma unroll
            for (int np = 0; np < 4; ++np) {
                uint32_t bh[4], bl[4];
                int boe = kOffE + np * 16 * FPITCH + kb * 16;
                LDSM4(bh[0], bh[1], bh[2], bh[3], khB + boe * 2);
                LDSM4(bl[0], bl[1], bl[2], bl[3], klB + boe * 2);
                MMA_BF16(s[2 * np], a0, bh[0], bh[1]);
                MMA_BF16(s[2 * np], a0, bl[0], bl[1]);
                MMA_BF16(s[2 * np], a1, bh[0], bh[1]);
                MMA_BF16(s[2 * np + 1], a0, bh[2], bh[3]);
                MMA_BF16(s[2 * np + 1], a0, bl[2], bl[3]);
                MMA_BF16(s[2 * np + 1], a1, bh[2], bh[3]);
            }
        }

        // ---- causal mask ----
        if (j0 + 63 > i0 + w * 16) {
#pragma unroll
            for (int nf = 0; nf < 8; ++nf) {
                int j = j0 + nf * 8 + ((lane & 3) << 1);
                if (j     > rg0)     s[nf][0] = -1e9f;
                if (j + 1 > rg0)     s[nf][1] = -1e9f;
                if (j     > rg0 + 8) s[nf][2] = -1e9f;
                if (j + 1 > rg0 + 8) s[nf][3] = -1e9f;
            }
        }

        // ---- online softmax ----
#pragma unroll
        for (int half = 0; half < 2; ++half) {
            const int e0 = half * 2, e1 = half * 2 + 1;
            float vmax = -1e9f;
#pragma unroll
            for (int nf = 0; nf < 8; ++nf)
                vmax = fmaxf(vmax, fmaxf(s[nf][e0], s[nf][e1]));
            vmax = fmaxf(vmax, __shfl_xor_sync(0xffffffffu, vmax, 1));
            vmax = fmaxf(vmax, __shfl_xor_sync(0xffffffffu, vmax, 2));
            float mnew = fmaxf(s_m[half], vmax);
            float corr = fast_exp(s_m[half] - mnew);
            float rsum = 0.f;
#pragma unroll
            for (int nf = 0; nf < 8; ++nf) {
                s[nf][e0] = fast_exp(s[nf][e0] - mnew);
                s[nf][e1] = fast_exp(s[nf][e1] - mnew);
                rsum += s[nf][e0] + s[nf][e1];
            }
            rsum += __shfl_xor_sync(0xffffffffu, rsum, 1);
            rsum += __shfl_xor_sync(0xffffffffu, rsum, 2);
            s_l[half] = s_l[half] * corr + rsum;
            s_m[half] = mnew;
#pragma unroll
            for (int nf = 0; nf < 8; ++nf) {
                o[nf][e0] *= corr;
                o[nf][e1] *= corr;
            }
        }

        // ---- O += P @ V ----
#pragma unroll
        for (int kc = 0; kc < 4; ++kc) {
            uint32_t ph[4], pl[4];
            split_pack(s[2 * kc][0],     s[2 * kc][1],     ph[0], pl[0]);
            split_pack(s[2 * kc][2],     s[2 * kc][3],     ph[1], pl[1]);
            split_pack(s[2 * kc + 1][0], s[2 * kc + 1][1], ph[2], pl[2]);
            split_pack(s[2 * kc + 1][2], s[2 * kc + 1][3], ph[3], pl[3]);
#pragma unroll
            for (int np = 0; np < 4; ++np) {
                uint32_t bh[4], bl[4];
                int voe = vOffE + kc * 16 * FPITCH + np * 16;
                LDSM4T(bh[0], bh[1], bh[2], bh[3], vhB + voe * 2);
                LDSM4T(bl[0], bl[1], bl[2], bl[3], vlB + voe * 2);
                MMA_BF16(o[2 * np], ph, bh[0], bh[1]);
                MMA_BF16(o[2 * np], ph, bl[0], bl[1]);
                MMA_BF16(o[2 * np], pl, bh[0], bh[1]);
                MMA_BF16(o[2 * np + 1], ph, bh[2], bh[3]);
                MMA_BF16(o[2 * np + 1], ph, bl[2], bl[3]);
                MMA_BF16(o[2 * np + 1], pl, bh[2], bh[3]);
            }
        }
        __syncthreads();   // stage reads done before next refill (and Q before reload)
    }

    // ---- finalize: write split-bf16 attn for the O-projection ----
    const float inv0 = 1.f / s_l[0];
    const float inv1 = 1.f / s_l[1];
#pragma unroll
    for (int nf = 0; nf < 8; ++nf) {
        int col = colbase + nf * 8 + ((lane & 3) << 1);
        float v0 = o[nf][0] * inv0, v1 = o[nf][1] * inv0;
        float v2 = o[nf][2] * inv1, v3 = o[nf][3] * inv1;
        uint32_t h01, l01, h23, l23;
        split_pack(v0, v1, h01, l01);
        split_pack(v2, v3, h23, l23);
        size_t r0off = ((size_t)rg0 * B_DIM + b) * E_DIM + col;
        size_t r1off = ((size_t)(rg0 + 8) * B_DIM + b) * E_DIM + col;
        *(uint32_t*)(gAh + r0off) = h01;
        *(uint32_t*)(gAl + r0off) = l01;
        *(uint32_t*)(gAh + r1off) = h23;
        *(uint32_t*)(gAl + r1off) = l23;
    }
}

__global__ void __launch_bounds__(256)
flash_mma_kernel()
{
    extern __shared__ char dynsm[];
    const uint32_t smb = smem_u32(dynsm);

    const int tid  = threadIdx.x;
    const int lane = tid & 31;
    const int w    = tid >> 5;
    const int pair = blockIdx.x;          // 0..7
    const int head = blockIdx.y;          // 0..31
    const int b    = head >> 4;
    const int h    = head & 15;
    const int colbase = h * DH;

    const int qOffE = (w * 16 + (lane & 15)) * FPITCH + ((lane >> 4) & 1) * 8;
    const int kOffE = ((lane & 7) + ((lane >> 4) & 1) * 8) * FPITCH + ((lane >> 3) & 1) * 8;
    const int vOffE = ((lane & 7) + ((lane >> 3) & 1) * 8) * FPITCH + ((lane >> 4) & 1) * 8;

    // balanced pair: (pair) and (15 - pair) -> 34 kv-tiles per CTA, uniform
    flash_one(pair,      smb, b, colbase, tid, lane, w, qOffE, kOffE, vOffE);
    flash_one(15 - pair, smb, b, colbase, tid, lane, w, qOffE, kOffE, vOffE);
}

// ===========================================================================
// kernel_launch
// Inputs: query, Wq, bq, Wk, bk, Wv, bv, Wo, bo, attn_mask (ignored: causal)
// ===========================================================================
extern "C" void kernel_launch(void* const* d_in, const int* in_sizes, int n_in,
                              void* d_out, int out_size)
{
    const float* query = (const float*)d_in[0];
    const float* bq    = (const float*)d_in[2];
    const float* bk    = (const float*)d_in[4];
    const float* bv    = (const float*)d_in[6];
    const float* bo    = (const float*)d_in[8];
    const float* Wq    = (const float*)d_in[1];
    const float* Wk    = (const float*)d_in[3];
    const float* Wv    = (const float*)d_in[5];
    const float* Wo    = (const float*)d_in[7];
    float* out = (float*)d_out;

    cudaFuncSetAttribute(qkv_kernel, cudaFuncAttributeMaxDynamicSharedMemorySize, GSMEM_BYTES);
    cudaFuncSetAttribute(oproj_kernel, cudaFuncAttributeMaxDynamicSharedMemorySize, GSMEM_BYTES);
    cudaFuncSetAttribute(flash_mma_kernel, cudaFuncAttributeMaxDynamicSharedMemorySize, FSMEM_BYTES);

    // split X and weights to bf16 hi/lo
    convert_kernel<<<8192, 256>>>(query, Wq, Wk, Wv, Wo);

    // QKV projections (z selects Q/K/V), outputs split bf16
    qkv_kernel<<<dim3(E_DIM / 128, MROWS / 128, 3), 256, GSMEM_BYTES>>>(bq, bk, bv);

    // causal flash attention: 8 balanced q-tile pairs x 32 heads
    flash_mma_kernel<<<dim3(8, B_DIM * H_DIM), 256, FSMEM_BYTES>>>();

    // output projection -> f32 out
    oproj_kernel<<<dim3(E_DIM / 128, MROWS / 128), 256, GSMEM_BYTES>>>(bo, out);
}

// round 6
// speedup vs baseline: 3.4580x; 1.0059x over previous
#include <cuda_runtime.h>
#include <cuda_bf16.h>
#include <math.h>
#include <stdint.h>

// Problem constants
#define T_DIM 2048
#define B_DIM 2
#define E_DIM 1024
#define H_DIM 16
#define DH    64
#define MROWS (T_DIM * B_DIM)   // 4096
#define NELEM (MROWS * E_DIM)   // 4194304

// Scratch: split-bf16 operands (device globals — no allocation allowed)
__device__ __nv_bfloat16 gXh[NELEM], gXl[NELEM];           // input X split
__device__ __nv_bfloat16 gWh[NELEM], gWl[NELEM];           // Wq,Wk,Wv,Wo (1M each)
__device__ __nv_bfloat16 gQh[NELEM], gQl[NELEM];
__device__ __nv_bfloat16 gKh[NELEM], gKl[NELEM];
__device__ __nv_bfloat16 gVh[NELEM], gVl[NELEM];
__device__ __nv_bfloat16 gAh[NELEM], gAl[NELEM];           // attn output split

// ===========================================================================
// Helpers
// ===========================================================================
__device__ __forceinline__ uint32_t smem_u32(const void* p) {
    uint32_t a;
    asm("{ .reg .u64 t; cvta.to.shared.u64 t, %1; cvt.u32.u64 %0, t; }" : "=r"(a) : "l"(p));
    return a;
}

#define LDSM4(R0, R1, R2, R3, ADDR) \
    asm volatile("ldmatrix.sync.aligned.m8n8.x4.shared.b16 {%0,%1,%2,%3}, [%4];" \
                 : "=r"(R0), "=r"(R1), "=r"(R2), "=r"(R3) : "r"(ADDR))

#define LDSM4T(R0, R1, R2, R3, ADDR) \
    asm volatile("ldmatrix.sync.aligned.m8n8.x4.trans.shared.b16 {%0,%1,%2,%3}, [%4];" \
                 : "=r"(R0), "=r"(R1), "=r"(R2), "=r"(R3) : "r"(ADDR))

#define MMA_BF16(D, A, B0, B1) \
    asm volatile("mma.sync.aligned.m16n8k16.row.col.f32.bf16.bf16.f32 " \
                 "{%0,%1,%2,%3}, {%4,%5,%6,%7}, {%8,%9}, {%0,%1,%2,%3};" \
                 : "+f"((D)[0]), "+f"((D)[1]), "+f"((D)[2]), "+f"((D)[3]) \
                 : "r"((A)[0]), "r"((A)[1]), "r"((A)[2]), "r"((A)[3]), "r"(B0), "r"(B1))

#define CP_ASYNC16(DST, SRC) \
    asm volatile("cp.async.cg.shared.global [%0], [%1], 16;" :: "r"(DST), "l"(SRC) : "memory")
#define CP_COMMIT() asm volatile("cp.async.commit_group;" ::: "memory")
#define CP_WAIT(N)  asm volatile("cp.async.wait_group %0;" :: "n"(N) : "memory")

// pack two f32 into bf16x2 hi + residual lo
__device__ __forceinline__ void split_pack(float a, float b, uint32_t& hi, uint32_t& lo) {
    __nv_bfloat162 H, L;
    H.x = __float2bfloat16(a); H.y = __float2bfloat16(b);
    L.x = __float2bfloat16(a - __bfloat162float(H.x));
    L.y = __float2bfloat16(b - __bfloat162float(H.y));
    hi = *(uint32_t*)&H; lo = *(uint32_t*)&L;
}

// fast exp on FMA pipe (no MUFU)
__device__ __forceinline__ float fast_exp(float x) {
    float y = fmaxf(x * 1.44269504f, -126.0f);
    int   e = __float2int_rn(y);
    float f = y - (float)e;
    float p = 1.33336e-3f;
    p = fmaf(p, f, 9.61812e-3f);
    p = fmaf(p, f, 5.55041e-2f);
    p = fmaf(p, f, 2.402265e-1f);
    p = fmaf(p, f, 6.931472e-1f);
    p = fmaf(p, f, 1.0f);
    return __int_as_float((e + 127) << 23) * p;
}

// ===========================================================================
// Convert kernel: split X and the 4 weight matrices into hi/lo bf16 globals.
// ===========================================================================
__global__ void __launch_bounds__(256)
convert_kernel(const float* __restrict__ X,
               const float* __restrict__ Wq, const float* __restrict__ Wk,
               const float* __restrict__ Wv, const float* __restrict__ Wo)
{
    int i = blockIdx.x * 256 + threadIdx.x;       // 0 .. 2097151
    const float4* src;
    __nv_bfloat16 *dh, *dl;
    int off;
    if (i < 1048576) {
        src = (const float4*)X; dh = gXh; dl = gXl; off = i;
    } else {
        int j = i - 1048576;
        int r = j >> 18;                           // 0..3 -> Wq,Wk,Wv,Wo
        off = j & 0x3FFFF;
        src = (const float4*)(r == 0 ? Wq : r == 1 ? Wk : r == 2 ? Wv : Wo);
        dh = gWh + ((size_t)r << 20);
        dl = gWl + ((size_t)r << 20);
    }
    float4 v = src[off];
    uint32_t h01, l01, h23, l23;
    split_pack(v.x, v.y, h01, l01);
    split_pack(v.z, v.w, h23, l23);
    *(uint2*)(dh + (size_t)off * 4) = make_uint2(h01, h23);
    *(uint2*)(dl + (size_t)off * 4) = make_uint2(l01, l23);
}

// ===========================================================================
// GEMM on tensor cores: C = (A @ W^T + bias) * alpha, split-bf16 operands.
// CTA 128x128, 8 warps (2x4), BK=32, 2-stage cp.async pipeline, 2 CTAs/SM.
// MMAs scheduled term-major: same-accumulator distance = 4.
// ===========================================================================
#define GPITCH 40
#define GARR_E (128 * GPITCH)          // 5120 elems per array
#define GSTAGE_E (4 * GARR_E)          // 20480 elems per stage
#define GS 2
#define GSMEM_BYTES (GS * GSTAGE_E * 2)  // 81920

__device__ __forceinline__ void gemm_produce(
    uint32_t smb, int stage,
    const __nv_bfloat16* __restrict__ Ah, const __nv_bfloat16* __restrict__ Al,
    const __nv_bfloat16* __restrict__ Bh, const __nv_bfloat16* __restrict__ Bl,
    int row0, int col0, int k0, int tid)
{
#pragma unroll
    for (int i = 0; i < 8; ++i) {
        int id  = tid + i * 256;         // 0..2047
        int arr = id >> 9;               // 0:Ah 1:Al 2:Bh 3:Bl
        int rid = (id >> 2) & 127;
        int cc  = id & 3;
        const __nv_bfloat16* g = (arr == 0) ? Ah : (arr == 1) ? Al : (arr == 2) ? Bh : Bl;
        int grow = ((arr < 2) ? row0 : col0) + rid;
        const __nv_bfloat16* src = g + (size_t)grow * E_DIM + k0 + cc * 8;
        uint32_t dst = smb + (uint32_t)(stage * GSTAGE_E + arr * GARR_E + rid * GPITCH + cc * 8) * 2;
        CP_ASYNC16(dst, src);
    }
}

template <int MODE>
__device__ __forceinline__ void gemm_cp(
    const __nv_bfloat16* __restrict__ Ah, const __nv_bfloat16* __restrict__ Al,
    const __nv_bfloat16* __restrict__ Bh, const __nv_bfloat16* __restrict__ Bl,
    const float* __restrict__ bias, float alpha,
    float* __restrict__ Cf,
    __nv_bfloat16* __restrict__ Ch, __nv_bfloat16* __restrict__ Cl)
{
    extern __shared__ char dynsm[];
    const uint32_t smb = smem_u32(dynsm);
    const int tid  = threadIdx.x;
    const int lane = tid & 31;
    const int wid  = tid >> 5;
    const int wy   = wid >> 2;
    const int wx   = wid & 3;
    const int row0 = blockIdx.y * 128;
    const int col0 = blockIdx.x * 128;

    const int aOffE = (wy * 64 + (lane & 15)) * GPITCH + ((lane >> 4) & 1) * 8;
    const int bOffE = (wx * 32 + (lane & 7) + ((lane >> 4) & 1) * 8) * GPITCH + ((lane >> 3) & 1) * 8;

    float acc[4][4][4];
#pragma unroll
    for (int i = 0; i < 4; i++)
#pragma unroll
        for (int j = 0; j < 4; j++)
#pragma unroll
            for (int k = 0; k < 4; k++) acc[i][j][k] = 0.f;

    // prologue: stage 0 <- chunk 0
    gemm_produce(smb, 0, Ah, Al, Bh, Bl, row0, col0, 0, tid);
    CP_COMMIT();

    for (int c = 0; c < 32; ++c) {
        // prefetch chunk c+1 into the other stage
        if (c + 1 < 32) {
            gemm_produce(smb, (c + 1) & 1, Ah, Al, Bh, Bl, row0, col0, (c + 1) * 32, tid);
            CP_COMMIT();
            CP_WAIT(1);
        } else {
            CP_WAIT(0);
        }
        __syncthreads();

        const uint32_t stA = smb + (uint32_t)((c & 1) * GSTAGE_E) * 2;
        const uint32_t aHb = stA;
        const uint32_t aLb = stA + GARR_E * 2;
        const uint32_t bHb = stA + 2 * GARR_E * 2;
        const uint32_t bLb = stA + 3 * GARR_E * 2;

#pragma unroll
        for (int kb = 0; kb < 2; ++kb) {
            uint32_t bh[4][2], bl[4][2];
#pragma unroll
            for (int np = 0; np < 2; ++np) {
                int boe = bOffE + np * 16 * GPITCH + kb * 16;
                LDSM4(bh[2 * np][0], bh[2 * np][1], bh[2 * np + 1][0], bh[2 * np + 1][1],
                      bHb + boe * 2);
                LDSM4(bl[2 * np][0], bl[2 * np][1], bl[2 * np + 1][0], bl[2 * np + 1][1],
                      bLb + boe * 2);
            }
#pragma unroll
            for (int mf = 0; mf < 4; ++mf) {
                uint32_t ah[4], al[4];
                int aoe = aOffE + mf * 16 * GPITCH + kb * 16;
                LDSM4(ah[0], ah[1], ah[2], ah[3], aHb + aoe * 2);
                LDSM4(al[0], al[1], al[2], al[3], aLb + aoe * 2);
                // term-major: consecutive MMAs hit different accumulators
                MMA_BF16(acc[mf][0], ah, bh[0][0], bh[0][1]);
                MMA_BF16(acc[mf][1], ah, bh[1][0], bh[1][1]);
                MMA_BF16(acc[mf][2], ah, bh[2][0], bh[2][1]);
                MMA_BF16(acc[mf][3], ah, bh[3][0], bh[3][1]);
                MMA_BF16(acc[mf][0], ah, bl[0][0], bl[0][1]);
                MMA_BF16(acc[mf][1], ah, bl[1][0], bl[1][1]);
                MMA_BF16(acc[mf][2], ah, bl[2][0], bl[2][1]);
                MMA_BF16(acc[mf][3], ah, bl[3][0], bl[3][1]);
                MMA_BF16(acc[mf][0], al, bh[0][0], bh[0][1]);
                MMA_BF16(acc[mf][1], al, bh[1][0], bh[1][1]);
                MMA_BF16(acc[mf][2], al, bh[2][0], bh[2][1]);
                MMA_BF16(acc[mf][3], al, bh[3][0], bh[3][1]);
            }
        }
        __syncthreads();   // all reads of this stage done before it is refilled
    }

    // epilogue
#pragma unroll
    for (int mf = 0; mf < 4; ++mf) {
        int r = row0 + wy * 64 + mf * 16 + (lane >> 2);
#pragma unroll
        for (int nf = 0; nf < 4; ++nf) {
            int col = col0 + wx * 32 + nf * 8 + ((lane & 3) << 1);
            float b0 = bias[col], b1 = bias[col + 1];
            float v0 = (acc[mf][nf][0] + b0) * alpha;
            float v1 = (acc[mf][nf][1] + b1) * alpha;
            float v2 = (acc[mf][nf][2] + b0) * alpha;
            float v3 = (acc[mf][nf][3] + b1) * alpha;
            if (MODE == 0) {
                *(float2*)(Cf + (size_t)r * E_DIM + col)       = make_float2(v0, v1);
                *(float2*)(Cf + (size_t)(r + 8) * E_DIM + col) = make_float2(v2, v3);
            } else {
                uint32_t h01, l01, h23, l23;
                split_pack(v0, v1, h01, l01);
                split_pack(v2, v3, h23, l23);
                *(uint32_t*)(Ch + (size_t)r * E_DIM + col)       = h01;
                *(uint32_t*)(Cl + (size_t)r * E_DIM + col)       = l01;
                *(uint32_t*)(Ch + (size_t)(r + 8) * E_DIM + col) = h23;
                *(uint32_t*)(Cl + (size_t)(r + 8) * E_DIM + col) = l23;
            }
        }
    }
}

__global__ void __launch_bounds__(256, 2)
qkv_kernel(const float* __restrict__ bq, const float* __restrict__ bk,
           const float* __restrict__ bv)
{
    const int z = blockIdx.z;
    const __nv_bfloat16* Bh = gWh + ((size_t)z << 20);
    const __nv_bfloat16* Bl = gWl + ((size_t)z << 20);
    if (z == 0)      gemm_cp<1>(gXh, gXl, Bh, Bl, bq, 0.125f, nullptr, gQh, gQl);
    else if (z == 1) gemm_cp<1>(gXh, gXl, Bh, Bl, bk, 1.0f,   nullptr, gKh, gKl);
    else             gemm_cp<1>(gXh, gXl, Bh, Bl, bv, 1.0f,   nullptr, gVh, gVl);
}

__global__ void __launch_bounds__(256, 2)
oproj_kernel(const float* __restrict__ bo, float* __restrict__ out)
{
    gemm_cp<0>(gAh, gAl, gWh + ((size_t)3 << 20), gWl + ((size_t)3 << 20),
               bo, 1.0f, out, nullptr, nullptr);
}

// ===========================================================================
// Flash attention on tensor cores (causal), split-bf16 inputs via cp.async.
// BR=128 (8 warps x m16), BC=64, Dh=64. Double-buffered K/V tiles.
// Balanced q-tile pairs; term-major MMA scheduling (same-acc distance = 8).
// ===========================================================================
#define FPITCH 72
#define FQ_E   (128 * FPITCH)              // 9216 per Q array
#define FKV_E  (64 * FPITCH)               // 4608 per KV array
#define FSTAGE_E (4 * FKV_E)               // 18432 per stage
#define FKV0_E (2 * FQ_E)                  // 18432 (stage area starts here)
#define FSMEM_BYTES ((FKV0_E + 2 * FSTAGE_E) * 2)   // 110592

__device__ __forceinline__ void flash_kv_produce(uint32_t smb, int stage, int j0,
                                                 int b, int colbase, int tid)
{
#pragma unroll
    for (int i = 0; i < 8; ++i) {
        int id  = tid + i * 256;
        int arr = id >> 9;                // 0:Kh 1:Kl 2:Vh 3:Vl
        int rid = (id >> 3) & 63;
        int cc  = id & 7;
        const __nv_bfloat16* g = (arr == 0) ? gKh : (arr == 1) ? gKl : (arr == 2) ? gVh : gVl;
        const __nv_bfloat16* src = g + ((size_t)(j0 + rid) * B_DIM + b) * E_DIM + colbase + cc * 8;
        uint32_t dst = smb + (uint32_t)(FKV0_E + stage * FSTAGE_E + arr * FKV_E + rid * FPITCH + cc * 8) * 2;
        CP_ASYNC16(dst, src);
    }
}

__device__ __forceinline__ void flash_one(int qt, uint32_t smb, int b, int colbase,
                                          int tid, int lane, int w,
                                          int qOffE, int kOffE, int vOffE)
{
    const int i0 = qt * 128;
    const int ktmax = 2 * qt + 1;

    // prologue: Q tile (both splits) + KV stage 0 in one cp.async group
#pragma unroll
    for (int i = 0; i < 8; ++i) {
        int id  = tid + i * 256;          // 0..2047
        int arr = id >> 10;               // 0:Qh 1:Ql
        int rid = (id >> 3) & 127;
        int cc  = id & 7;
        const __nv_bfloat16* g = arr ? gQl : gQh;
        const __nv_bfloat16* src = g + ((size_t)(i0 + rid) * B_DIM + b) * E_DIM + colbase + cc * 8;
        uint32_t dst = smb + (uint32_t)(arr * FQ_E + rid * FPITCH + cc * 8) * 2;
        CP_ASYNC16(dst, src);
    }
    flash_kv_produce(smb, 0, 0, b, colbase, tid);
    CP_COMMIT();

    float s_m[2] = {-1e9f, -1e9f};
    float s_l[2] = {0.f, 0.f};
    float o[8][4];
#pragma unroll
    for (int i = 0; i < 8; i++)
#pragma unroll
        for (int j = 0; j < 4; j++) o[i][j] = 0.f;

    const int rg0 = i0 + w * 16 + (lane >> 2);
    const uint32_t qhB = smb;
    const uint32_t qlB = smb + FQ_E * 2;

    for (int kt = 0; kt <= ktmax; ++kt) {
        // prefetch next KV tile, keep it in flight while computing this one
        if (kt + 1 <= ktmax) {
            flash_kv_produce(smb, (kt + 1) & 1, (kt + 1) * 64, b, colbase, tid);
            CP_COMMIT();
            CP_WAIT(1);
        } else {
            CP_WAIT(0);
        }
        __syncthreads();

        const int j0 = kt * 64;
        const uint32_t stKV = smb + (uint32_t)(FKV0_E + (kt & 1) * FSTAGE_E) * 2;
        const uint32_t khB = stKV;
        const uint32_t klB = stKV + FKV_E * 2;
        const uint32_t vhB = stKV + 2 * FKV_E * 2;
        const uint32_t vlB = stKV + 3 * FKV_E * 2;

        // ---- S = Q @ K^T (term-major) ----
        float s[8][4];
#pragma unroll
        for (int i = 0; i < 8; i++)
#pragma unroll
            for (int j = 0; j < 4; j++) s[i][j] = 0.f;

#pragma unroll
        for (int kb = 0; kb < 4; ++kb) {
            uint32_t a0[4], a1[4];
            int aoe = qOffE + kb * 16;
            LDSM4(a0[0], a0[1], a0[2], a0[3], qhB + aoe * 2);
            LDSM4(a1[0], a1[1], a1[2], a1[3], qlB + aoe * 2);
            uint32_t bh[4][4], bl[4][4];
#pragma unroll
            for (int np = 0; np < 4; ++np) {
                int boe = kOffE + np * 16 * FPITCH + kb * 16;
                LDSM4(bh[np][0], bh[np][1], bh[np][2], bh[np][3], khB + boe * 2);
                LDSM4(bl[np][0], bl[np][1], bl[np][2], bl[np][3], klB + boe * 2);
            }
            // term 1: a0 * bh  (8 distinct accumulators)
#pragma unroll
            for (int np = 0; np < 4; ++np) {
                MMA_BF16(s[2 * np],     a0, bh[np][0], bh[np][1]);
                MMA_BF16(s[2 * np + 1], a0, bh[np][2], bh[np][3]);
            }
            // term 2: a0 * bl
#pragma unroll
            for (int np = 0; np < 4; ++np) {
                MMA_BF16(s[2 * np],     a0, bl[np][0], bl[np][1]);
                MMA_BF16(s[2 * np + 1], a0, bl[np][2], bl[np][3]);
            }
            // term 3: a1 * bh
#pragma unroll
            for (int np = 0; np < 4; ++np) {
                MMA_BF16(s[2 * np],     a1, bh[np][0], bh[np][1]);
                MMA_BF16(s[2 * np + 1], a1, bh[np][2], bh[np][3]);
            }
        }

        // ---- causal mask ----
        if (j0 + 63 > i0 + w * 16) {
#pragma unroll
            for (int nf = 0; nf < 8; ++nf) {
                int j = j0 + nf * 8 + ((lane & 3) << 1);
                if (j     > rg0)     s[nf][0] = -1e9f;
                if (j + 1 > rg0)     s[nf][1] = -1e9f;
                if (j     > rg0 + 8) s[nf][2] = -1e9f;
                if (j + 1 > rg0 + 8) s[nf][3] = -1e9f;
            }
        }

        // ---- online softmax ----
#pragma unroll
        for (int half = 0; half < 2; ++half) {
            const int e0 = half * 2, e1 = half * 2 + 1;
            float vmax = -1e9f;
#pragma unroll
            for (int nf = 0; nf < 8; ++nf)
                vmax = fmaxf(vmax, fmaxf(s[nf][e0], s[nf][e1]));
            vmax = fmaxf(vmax, __shfl_xor_sync(0xffffffffu, vmax, 1));
            vmax = fmaxf(vmax, __shfl_xor_sync(0xffffffffu, vmax, 2));
            float mnew = fmaxf(s_m[half], vmax);
            float corr = fast_exp(s_m[half] - mnew);
            float rsum = 0.f;
#pragma unroll
            for (int nf = 0; nf < 8; ++nf) {
                s[nf][e0] = fast_exp(s[nf][e0] - mnew);
                s[nf][e1] = fast_exp(s[nf][e1] - mnew);
                rsum += s[nf][e0] + s[nf][e1];
            }
            rsum += __shfl_xor_sync(0xffffffffu, rsum, 1);
            rsum += __shfl_xor_sync(0xffffffffu, rsum, 2);
            s_l[half] = s_l[half] * corr + rsum;
            s_m[half] = mnew;
#pragma unroll
            for (int nf = 0; nf < 8; ++nf) {
                o[nf][e0] *= corr;
                o[nf][e1] *= corr;
            }
        }

        // ---- O += P @ V (term-major) ----
#pragma unroll
        for (int kc = 0; kc < 4; ++kc) {
            uint32_t ph[4], pl[4];
            split_pack(s[2 * kc][0],     s[2 * kc][1],     ph[0], pl[0]);
            split_pack(s[2 * kc][2],     s[2 * kc][3],     ph[1], pl[1]);
            split_pack(s[2 * kc + 1][0], s[2 * kc + 1][1], ph[2], pl[2]);
            split_pack(s[2 * kc + 1][2], s[2 * kc + 1][3], ph[3], pl[3]);
            uint32_t wh[4][4], wl[4][4];
#pragma unroll
            for (int np = 0; np < 4; ++np) {
                int voe = vOffE + kc * 16 * FPITCH + np * 16;
                LDSM4T(wh[np][0], wh[np][1], wh[np][2], wh[np][3], vhB + voe * 2);
                LDSM4T(wl[np][0], wl[np][1], wl[np][2], wl[np][3], vlB + voe * 2);
            }
            // term 1: ph * vh
#pragma unroll
            for (int np = 0; np < 4; ++np) {
                MMA_BF16(o[2 * np],     ph, wh[np][0], wh[np][1]);
                MMA_BF16(o[2 * np + 1], ph, wh[np][2], wh[np][3]);
            }
            // term 2: pl * vh
#pragma unroll
            for (int np = 0; np < 4; ++np) {
                MMA_BF16(o[2 * np],     pl, wh[np][0], wh[np][1]);
                MMA_BF16(o[2 * np + 1], pl, wh[np][2], wh[np][3]);
            }
            // term 3: ph * vl
#pragma unroll
            for (int np = 0; np < 4; ++np) {
                MMA_BF16(o[2 * np],     ph, wl[np][0], wl[np][1]);
                MMA_BF16(o[2 * np + 1], ph, wl[np][2], wl[np][3]);
            }
        }
        __syncthreads();   // stage reads done before next refill (and Q before reload)
    }

    // ---- finalize: write split-bf16 attn for the O-projection ----
    const float inv0 = 1.f / s_l[0];
    const float inv1 = 1.f / s_l[1];
#pragma unroll
    for (int nf = 0; nf < 8; ++nf) {
        int col = colbase + nf * 8 + ((lane & 3) << 1);
        float v0 = o[nf][0] * inv0, v1 = o[nf][1] * inv0;
        float v2 = o[nf][2] * inv1, v3 = o[nf][3] * inv1;
        uint32_t h01, l01, h23, l23;
        split_pack(v0, v1, h01, l01);
        split_pack(v2, v3, h23, l23);
        size_t r0off = ((size_t)rg0 * B_DIM + b) * E_DIM + col;
        size_t r1off = ((size_t)(rg0 + 8) * B_DIM + b) * E_DIM + col;
        *(uint32_t*)(gAh + r0off) = h01;
        *(uint32_t*)(gAl + r0off) = l01;
        *(uint32_t*)(gAh + r1off) = h23;
        *(uint32_t*)(gAl + r1off) = l23;
    }
}

__global__ void __launch_bounds__(256)
flash_mma_kernel()
{
    extern __shared__ char dynsm[];
    const uint32_t smb = smem_u32(dynsm);

    const int tid  = threadIdx.x;
    const int lane = tid & 31;
    const int w    = tid >> 5;
    const int pair = blockIdx.x;          // 0..7
    const int head = blockIdx.y;          // 0..31
    const int b    = head >> 4;
    const int h    = head & 15;
    const int colbase = h * DH;

    const int qOffE = (w * 16 + (lane & 15)) * FPITCH + ((lane >> 4) & 1) * 8;
    const int kOffE = ((lane & 7) + ((lane >> 4) & 1) * 8) * FPITCH + ((lane >> 3) & 1) * 8;
    const int vOffE = ((lane & 7) + ((lane >> 3) & 1) * 8) * FPITCH + ((lane >> 4) & 1) * 8;

    // balanced pair: (pair) and (15 - pair) -> 34 kv-tiles per CTA, uniform
    flash_one(pair,      smb, b, colbase, tid, lane, w, qOffE, kOffE, vOffE);
    flash_one(15 - pair, smb, b, colbase, tid, lane, w, qOffE, kOffE, vOffE);
}

// ===========================================================================
// kernel_launch
// Inputs: query, Wq, bq, Wk, bk, Wv, bv, Wo, bo, attn_mask (ignored: causal)
// ===========================================================================
extern "C" void kernel_launch(void* const* d_in, const int* in_sizes, int n_in,
                              void* d_out, int out_size)
{
    const float* query = (const float*)d_in[0];
    const float* Wq    = (const float*)d_in[1];
    const float* bq    = (const float*)d_in[2];
    const float* Wk    = (const float*)d_in[3];
    const float* bk    = (const float*)d_in[4];
    const float* Wv    = (const float*)d_in[5];
    const float* bv    = (const float*)d_in[6];
    const float* Wo    = (const float*)d_in[7];
    const float* bo    = (const float*)d_in[8];
    float* out = (float*)d_out;

    cudaFuncSetAttribute(qkv_kernel, cudaFuncAttributeMaxDynamicSharedMemorySize, GSMEM_BYTES);
    cudaFuncSetAttribute(oproj_kernel, cudaFuncAttributeMaxDynamicSharedMemorySize, GSMEM_BYTES);
    cudaFuncSetAttribute(flash_mma_kernel, cudaFuncAttributeMaxDynamicSharedMemorySize, FSMEM_BYTES);

    // split X and weights to bf16 hi/lo
    convert_kernel<<<8192, 256>>>(query, Wq, Wk, Wv, Wo);

    // QKV projections (z selects Q/K/V), outputs split bf16
    qkv_kernel<<<dim3(E_DIM / 128, MROWS / 128, 3), 256, GSMEM_BYTES>>>(bq, bk, bv);

    // causal flash attention: 8 balanced q-tile pairs x 32 heads
    flash_mma_kernel<<<dim3(8, B_DIM * H_DIM), 256, FSMEM_BYTES>>>();

    // output projection -> f32 out
    oproj_kernel<<<dim3(E_DIM / 128, MROWS / 128), 256, GSMEM_BYTES>>>(bo, out);
}